// round 9
// baseline (speedup 1.0000x reference)
#include <cuda_runtime.h>
#include <math.h>

#define TPB 352
typedef unsigned long long u64;

// ---- packed fp32x2 helpers (sm_103a) ----
__device__ __forceinline__ u64 packdup(float a) {
    u64 r; asm("mov.b64 %0,{%1,%1};" : "=l"(r) : "f"(a)); return r;
}
__device__ __forceinline__ u64 fma2(u64 a, u64 b, u64 c) {
    u64 d; asm("fma.rn.f32x2 %0,%1,%2,%3;" : "=l"(d) : "l"(a), "l"(b), "l"(c)); return d;
}
__device__ __forceinline__ void unpk(u64 x, float& lo, float& hi) {
    asm("mov.b64 {%0,%1},%2;" : "=f"(lo), "=f"(hi) : "l"(x));
}

// ---- shared memory layout (floats) ----
// conv weights as (pairs of taps -> LDS.128) + (single last tap -> LDS.64)
#define OFF_W1PR 0       // [4cp][7row][3 pair][2 u64]  (336)
#define OFF_W1S  336     // [4cp][7row] u64             (56)  -> 392
#define OFF_W2PR 392     // [5cp][8ci][5row][2 pair][2 u64] (1600) -> 1992
#define OFF_W2S  1992    // [5cp][8ci][5row] u64        (400) -> 2392
#define OFF_CWPR 2392    // [10cp][10ci][5row][2 pair][2 u64] (4000) -> 6392
#define OFF_CWS  6392    // [10cp][10ci][5row] u64      (1000) -> 7392
#define OFF_B1P  7392    // (8)
#define OFF_B2P  7400    // (10)
#define OFF_CBP  7410    // (20) -> 7430 pad 7432
// per-image blocks (x2)
#define SH_IMG0 7432
#define IMG_STRIDE 3176
#define PX   0                // [28][28] (784)
#define PBUF 784              // pooled1 [8][11][12]=1056 / pooled3 [10][13][14]=1820
#define PF   2604             // (90)
#define PH   2694             // (32)
#define PK   2726             // (40) -> 2766 pad 2768
#define PP4  2768             // [20][4][4] (320)
#define PY1  3088             // (64)
#define PLG  3152             // (16) -> 3168
#define SMEM_FLOATS (SH_IMG0 + 2 * IMG_STRIDE)
#define SMEM_BYTES  (SMEM_FLOATS * 4)

__global__ __launch_bounds__(TPB, 4) void fused_net_kernel(
    const float* __restrict__ x,
    const float* __restrict__ kf_w1, const float* __restrict__ kf_b1,
    const float* __restrict__ kf_w2, const float* __restrict__ kf_b2,
    const float* __restrict__ kf_fc1_w, const float* __restrict__ kf_fc1_b,
    const float* __restrict__ kf_fc2_w, const float* __restrict__ kf_fc2_b,
    const float* __restrict__ conv2_w, const float* __restrict__ conv2_b,
    const float* __restrict__ fc1_w, const float* __restrict__ fc1_b,
    const float* __restrict__ fc2_w, const float* __restrict__ fc2_b,
    float* __restrict__ out, int N)
{
    extern __shared__ __align__(16) float s[];

    const int bn  = blockIdx.x;
    const int tid = threadIdx.x;
    const int i0  = 2 * bn;
    const int warp = tid >> 5;
    const int lane = tid & 31;

    // ================= Stage 0: stage inputs into smem =================
    {
        #pragma unroll
        for (int img = 0; img < 2; img++) {
            if (i0 + img < N) {
                const float4* x4 = (const float4*)(x + (i0 + img) * 784);
                float4* sx4 = (float4*)(s + SH_IMG0 + img * IMG_STRIDE + PX);
                for (int i = tid; i < 196; i += TPB) sx4[i] = x4[i];
            }
        }
        // kf_w1: c=out ch (0..7), tap q=row*7+v
        for (int i = tid; i < 392; i += TPB) {
            int c = i / 49, q = i - c * 49;
            int row = q / 7, v = q - row * 7;
            int cp = c >> 1, ch = c & 1;
            if (v < 6)
                s[OFF_W1PR + ((cp * 7 + row) * 3 + (v >> 1)) * 4 + (v & 1) * 2 + ch] = kf_w1[i];
            else
                s[OFF_W1S + (cp * 7 + row) * 2 + ch] = kf_w1[i];
        }
        // kf_w2: c=out ch (0..9), ci=in ch (0..7), tap q=row*5+v
        for (int i = tid; i < 2000; i += TPB) {
            int c = i / 200, r200 = i - c * 200;
            int ci = r200 / 25, q = r200 - ci * 25;
            int row = q / 5, v = q - row * 5;
            int cp = c >> 1, ch = c & 1;
            if (v < 4)
                s[OFF_W2PR + (((cp * 8 + ci) * 5 + row) * 2 + (v >> 1)) * 4 + (v & 1) * 2 + ch] = kf_w2[i];
            else
                s[OFF_W2S + ((cp * 8 + ci) * 5 + row) * 2 + ch] = kf_w2[i];
        }
        // conv2_w: c=out ch (0..19), ci (0..9), tap q=row*5+v
        for (int i = tid; i < 5000; i += TPB) {
            int c = i / 250, r250 = i - c * 250;
            int ci = r250 / 25, q = r250 - ci * 25;
            int row = q / 5, v = q - row * 5;
            int cp = c >> 1, ch = c & 1;
            if (v < 4)
                s[OFF_CWPR + (((cp * 10 + ci) * 5 + row) * 2 + (v >> 1)) * 4 + (v & 1) * 2 + ch] = conv2_w[i];
            else
                s[OFF_CWS + ((cp * 10 + ci) * 5 + row) * 2 + ch] = conv2_w[i];
        }
        if (tid < 8)  s[OFF_B1P + tid] = kf_b1[tid];
        if (tid < 10) s[OFF_B2P + tid] = kf_b2[tid];
        if (tid < 20) s[OFF_CBP + tid] = conv2_b[tid];
    }
    __syncthreads();

    // ===== Stage 1: conv7x7 (1->8) + pool + relu -> pooled1 [8][11][12pad] =====
    for (int u = tid; u < 968; u += TPB) {
        const int img = u / 484;
        const int t   = u - img * 484;
        const int cp  = t / 121;
        const int r2  = t - cp * 121;
        const int pi  = r2 / 11;
        const int pj  = r2 - pi * 11;
        const float* sx = s + SH_IMG0 + img * IMG_STRIDE + PX;
        const ulonglong2* wpr = (const ulonglong2*)(s + OFF_W1PR) + cp * 7 * 3;
        const u64* ws = (const u64*)(s + OFF_W1S) + cp * 7;
        const u64 bias = ((const u64*)(s + OFF_B1P))[cp];
        u64 a00 = bias, a01 = bias, a10 = bias, a11 = bias;
        #pragma unroll
        for (int r = 0; r < 8; r++) {
            const float2* row = (const float2*)(sx + (2 * pi + r) * 28 + 2 * pj);
            u64 pd[8];
            #pragma unroll
            for (int j = 0; j < 4; j++) {
                float2 f = row[j];
                pd[2 * j]     = packdup(f.x);
                pd[2 * j + 1] = packdup(f.y);
            }
            if (r < 7) {
                const ulonglong2 P0 = wpr[r * 3 + 0];
                const ulonglong2 P1 = wpr[r * 3 + 1];
                const ulonglong2 P2 = wpr[r * 3 + 2];
                const u64 T6 = ws[r];
                a00 = fma2(pd[0], P0.x, a00); a01 = fma2(pd[1], P0.x, a01);
                a00 = fma2(pd[1], P0.y, a00); a01 = fma2(pd[2], P0.y, a01);
                a00 = fma2(pd[2], P1.x, a00); a01 = fma2(pd[3], P1.x, a01);
                a00 = fma2(pd[3], P1.y, a00); a01 = fma2(pd[4], P1.y, a01);
                a00 = fma2(pd[4], P2.x, a00); a01 = fma2(pd[5], P2.x, a01);
                a00 = fma2(pd[5], P2.y, a00); a01 = fma2(pd[6], P2.y, a01);
                a00 = fma2(pd[6], T6,   a00); a01 = fma2(pd[7], T6,   a01);
            }
            if (r >= 1) {
                const ulonglong2 P0 = wpr[(r - 1) * 3 + 0];
                const ulonglong2 P1 = wpr[(r - 1) * 3 + 1];
                const ulonglong2 P2 = wpr[(r - 1) * 3 + 2];
                const u64 T6 = ws[r - 1];
                a10 = fma2(pd[0], P0.x, a10); a11 = fma2(pd[1], P0.x, a11);
                a10 = fma2(pd[1], P0.y, a10); a11 = fma2(pd[2], P0.y, a11);
                a10 = fma2(pd[2], P1.x, a10); a11 = fma2(pd[3], P1.x, a11);
                a10 = fma2(pd[3], P1.y, a10); a11 = fma2(pd[4], P1.y, a11);
                a10 = fma2(pd[4], P2.x, a10); a11 = fma2(pd[5], P2.x, a11);
                a10 = fma2(pd[5], P2.y, a10); a11 = fma2(pd[6], P2.y, a11);
                a10 = fma2(pd[6], T6,   a10); a11 = fma2(pd[7], T6,   a11);
            }
        }
        float p0, p1, q0, q1, r0, r1, t0, t1;
        unpk(a00, p0, p1); unpk(a01, q0, q1); unpk(a10, r0, r1); unpk(a11, t0, t1);
        float m0 = fmaxf(fmaxf(p0, q0), fmaxf(r0, t0));
        float m1 = fmaxf(fmaxf(p1, q1), fmaxf(r1, t1));
        float* buf = s + SH_IMG0 + img * IMG_STRIDE + PBUF;
        buf[(2 * cp)     * 132 + pi * 12 + pj] = fmaxf(m0, 0.0f);
        buf[(2 * cp + 1) * 132 + pi * 12 + pj] = fmaxf(m1, 0.0f);
    }
    __syncthreads();

    // ===== Stage 2: conv5x5 (8->10) + pool + relu -> f [10][3][3] =====
    if (tid < 192) {
        const int uu   = tid >> 1;
        const int half = tid & 1;
        const bool valid = uu < 90;
        const int u   = valid ? uu : 0;
        const int img = u / 45;
        const int t   = u - img * 45;
        const int cp  = t / 9;
        const int pos = t - cp * 9;
        const int pi  = pos / 3;
        const int pj  = pos - pi * 3;
        const float* buf = s + SH_IMG0 + img * IMG_STRIDE + PBUF;
        const u64 bias = ((const u64*)(s + OFF_B2P))[cp];
        u64 A[4];
        #pragma unroll
        for (int k = 0; k < 4; k++) A[k] = half ? 0ull : bias;
        #pragma unroll
        for (int cc = 0; cc < 4; cc++) {
            const int ci = 4 * half + cc;
            const ulonglong2* wpr = (const ulonglong2*)(s + OFF_W2PR) + ((cp * 8 + ci) * 5) * 2;
            const u64* ws = (const u64*)(s + OFF_W2S) + (cp * 8 + ci) * 5;
            #pragma unroll
            for (int r = 0; r < 6; r++) {
                const float2* row = (const float2*)(buf + ci * 132 + (2 * pi + r) * 12 + 2 * pj);
                u64 pd[6];
                #pragma unroll
                for (int j = 0; j < 3; j++) {
                    float2 f = row[j];
                    pd[2 * j]     = packdup(f.x);
                    pd[2 * j + 1] = packdup(f.y);
                }
                if (r < 5) {
                    const ulonglong2 P0 = wpr[r * 2 + 0];
                    const ulonglong2 P1 = wpr[r * 2 + 1];
                    const u64 T4 = ws[r];
                    A[0] = fma2(pd[0], P0.x, A[0]); A[1] = fma2(pd[1], P0.x, A[1]);
                    A[0] = fma2(pd[1], P0.y, A[0]); A[1] = fma2(pd[2], P0.y, A[1]);
                    A[0] = fma2(pd[2], P1.x, A[0]); A[1] = fma2(pd[3], P1.x, A[1]);
                    A[0] = fma2(pd[3], P1.y, A[0]); A[1] = fma2(pd[4], P1.y, A[1]);
                    A[0] = fma2(pd[4], T4,   A[0]); A[1] = fma2(pd[5], T4,   A[1]);
                }
                if (r >= 1) {
                    const ulonglong2 P0 = wpr[(r - 1) * 2 + 0];
                    const ulonglong2 P1 = wpr[(r - 1) * 2 + 1];
                    const u64 T4 = ws[r - 1];
                    A[2] = fma2(pd[0], P0.x, A[2]); A[3] = fma2(pd[1], P0.x, A[3]);
                    A[2] = fma2(pd[1], P0.y, A[2]); A[3] = fma2(pd[2], P0.y, A[3]);
                    A[2] = fma2(pd[2], P1.x, A[2]); A[3] = fma2(pd[3], P1.x, A[3]);
                    A[2] = fma2(pd[3], P1.y, A[2]); A[3] = fma2(pd[4], P1.y, A[3]);
                    A[2] = fma2(pd[4], T4,   A[2]); A[3] = fma2(pd[5], T4,   A[3]);
                }
            }
        }
        float me = -INFINITY, mo = -INFINITY;
        #pragma unroll
        for (int k = 0; k < 4; k++) {
            float lo, hi;
            unpk(A[k], lo, hi);
            lo += __shfl_xor_sync(0xffffffffu, lo, 1);
            hi += __shfl_xor_sync(0xffffffffu, hi, 1);
            me = fmaxf(me, lo);
            mo = fmaxf(mo, hi);
        }
        if (valid) {
            float* f = s + SH_IMG0 + img * IMG_STRIDE + PF;
            if (half == 0) f[(2 * cp)     * 9 + pos] = fmaxf(me, 0.0f);
            else           f[(2 * cp + 1) * 9 + pos] = fmaxf(mo, 0.0f);
        }
    }
    __syncthreads();

    // ===== Stage 3a: hypernet fc1 90->32 relu — warp per output, global weights =====
    for (int u = warp; u < 64; u += (TPB / 32)) {
        const int img = u >> 5;
        const int o   = u & 31;
        const float* f  = s + SH_IMG0 + img * IMG_STRIDE + PF;
        const float* wr = kf_fc1_w + o * 90;
        float acc = 0.0f;
        #pragma unroll
        for (int k = 0; k < 3; k++) {
            const int q = lane + 32 * k;
            if (q < 90) acc = fmaf(f[q], wr[q], acc);
        }
        #pragma unroll
        for (int off = 16; off > 0; off >>= 1)
            acc += __shfl_xor_sync(0xffffffffu, acc, off);
        if (lane == 0)
            s[SH_IMG0 + img * IMG_STRIDE + PH + o] = fmaxf(acc + kf_fc1_b[o], 0.0f);
    }
    __syncthreads();

    // ===== Stage 3b: hypernet fc2 32->40 — warp per output, global weights =====
    for (int u = warp; u < 80; u += (TPB / 32)) {
        const int img = u / 40;
        const int o   = u - img * 40;
        const float* h = s + SH_IMG0 + img * IMG_STRIDE + PH;
        float acc = h[lane] * kf_fc2_w[o * 32 + lane];
        #pragma unroll
        for (int off = 16; off > 0; off >>= 1)
            acc += __shfl_xor_sync(0xffffffffu, acc, off);
        if (lane == 0)
            s[SH_IMG0 + img * IMG_STRIDE + PK + o] = acc + kf_fc2_b[o];
    }
    __syncthreads();

    // ===== Stage 4: dynamic 2x2 conv + pool + relu -> pooled3 [10][13][14pad] =====
    for (int it = tid; it < 3380; it += TPB) {
        const int img = it / 1690;
        const int t   = it - img * 1690;
        const int c   = t / 169;
        const int rem = t - c * 169;
        const int pi  = rem / 13;
        const int pj  = rem - pi * 13;
        const float* base = s + SH_IMG0 + img * IMG_STRIDE;
        const float k00 = base[PK + c * 4 + 0];
        const float k01 = base[PK + c * 4 + 1];
        const float k10 = base[PK + c * 4 + 2];
        const float k11 = base[PK + c * 4 + 3];
        float a[3][3];
        #pragma unroll
        for (int u2 = 0; u2 < 3; u2++) {
            const float2 f01 = *(const float2*)(base + PX + (2 * pi + u2) * 28 + 2 * pj);
            a[u2][0] = f01.x; a[u2][1] = f01.y;
            a[u2][2] = base[PX + (2 * pi + u2) * 28 + 2 * pj + 2];
        }
        float m = -INFINITY;
        #pragma unroll
        for (int di = 0; di < 2; di++)
            #pragma unroll
            for (int dj = 0; dj < 2; dj++) {
                float cv = a[di][dj] * k00;
                cv = fmaf(a[di][dj + 1],     k01, cv);
                cv = fmaf(a[di + 1][dj],     k10, cv);
                cv = fmaf(a[di + 1][dj + 1], k11, cv);
                m = fmaxf(m, cv);
            }
        s[SH_IMG0 + img * IMG_STRIDE + PBUF + c * 182 + pi * 14 + pj] = fmaxf(m, 0.0f);
    }
    __syncthreads();

    // ===== Stage 5: conv5x5 (10->20) + pool + relu -> pooled4 [20][4][4] =====
    if (tid < 320) {
        const int img = tid / 160;
        const int t   = tid - img * 160;
        const int cp  = t / 16;
        const int pos = t - cp * 16;
        const int pi  = pos / 4;
        const int pj  = pos - pi * 4;
        const float* buf = s + SH_IMG0 + img * IMG_STRIDE + PBUF;
        const u64 bias = ((const u64*)(s + OFF_CBP))[cp];
        u64 A[4] = {bias, bias, bias, bias};
        #pragma unroll 2
        for (int ci = 0; ci < 10; ci++) {
            const ulonglong2* wpr = (const ulonglong2*)(s + OFF_CWPR) + ((cp * 10 + ci) * 5) * 2;
            const u64* ws = (const u64*)(s + OFF_CWS) + (cp * 10 + ci) * 5;
            #pragma unroll
            for (int r = 0; r < 6; r++) {
                const float2* row = (const float2*)(buf + ci * 182 + (2 * pi + r) * 14 + 2 * pj);
                u64 pd[6];
                #pragma unroll
                for (int j = 0; j < 3; j++) {
                    float2 f = row[j];
                    pd[2 * j]     = packdup(f.x);
                    pd[2 * j + 1] = packdup(f.y);
                }
                if (r < 5) {
                    const ulonglong2 P0 = wpr[r * 2 + 0];
                    const ulonglong2 P1 = wpr[r * 2 + 1];
                    const u64 T4 = ws[r];
                    A[0] = fma2(pd[0], P0.x, A[0]); A[1] = fma2(pd[1], P0.x, A[1]);
                    A[0] = fma2(pd[1], P0.y, A[0]); A[1] = fma2(pd[2], P0.y, A[1]);
                    A[0] = fma2(pd[2], P1.x, A[0]); A[1] = fma2(pd[3], P1.x, A[1]);
                    A[0] = fma2(pd[3], P1.y, A[0]); A[1] = fma2(pd[4], P1.y, A[1]);
                    A[0] = fma2(pd[4], T4,   A[0]); A[1] = fma2(pd[5], T4,   A[1]);
                }
                if (r >= 1) {
                    const ulonglong2 P0 = wpr[(r - 1) * 2 + 0];
                    const ulonglong2 P1 = wpr[(r - 1) * 2 + 1];
                    const u64 T4 = ws[r - 1];
                    A[2] = fma2(pd[0], P0.x, A[2]); A[3] = fma2(pd[1], P0.x, A[3]);
                    A[2] = fma2(pd[1], P0.y, A[2]); A[3] = fma2(pd[2], P0.y, A[3]);
                    A[2] = fma2(pd[2], P1.x, A[2]); A[3] = fma2(pd[3], P1.x, A[3]);
                    A[2] = fma2(pd[3], P1.y, A[2]); A[3] = fma2(pd[4], P1.y, A[3]);
                    A[2] = fma2(pd[4], T4,   A[2]); A[3] = fma2(pd[5], T4,   A[3]);
                }
            }
        }
        float p0, p1, q0, q1, r0, r1, t0, t1;
        unpk(A[0], p0, p1); unpk(A[1], q0, q1); unpk(A[2], r0, r1); unpk(A[3], t0, t1);
        float m0 = fmaxf(fmaxf(p0, q0), fmaxf(r0, t0));
        float m1 = fmaxf(fmaxf(p1, q1), fmaxf(r1, t1));
        float* p4 = s + SH_IMG0 + img * IMG_STRIDE + PP4;
        p4[(2 * cp)     * 16 + pos] = fmaxf(m0, 0.0f);
        p4[(2 * cp + 1) * 16 + pos] = fmaxf(m1, 0.0f);
    }
    __syncthreads();

    // ===== Stage 6: fc1 320->50 relu, warp per (img,o), global weights =====
    for (int u = warp; u < 100; u += (TPB / 32)) {
        const int img = u / 50;
        const int o   = u - img * 50;
        const float4* wr = (const float4*)(fc1_w + o * 320);
        const float4* pr = (const float4*)(s + SH_IMG0 + img * IMG_STRIDE + PP4);
        float acc = 0.0f;
        #pragma unroll
        for (int k = 0; k < 3; k++) {
            const int i = lane + 32 * k;
            if (i < 80) {
                float4 w4 = wr[i];
                float4 p4 = pr[i];
                acc = fmaf(w4.x, p4.x, fmaf(w4.y, p4.y,
                      fmaf(w4.z, p4.z, fmaf(w4.w, p4.w, acc))));
            }
        }
        #pragma unroll
        for (int off = 16; off > 0; off >>= 1)
            acc += __shfl_xor_sync(0xffffffffu, acc, off);
        if (lane == 0)
            s[SH_IMG0 + img * IMG_STRIDE + PY1 + o] = fmaxf(acc + fc1_b[o], 0.0f);
    }
    __syncthreads();

    // ===== Stage 7: fc2 50->10 — warp per (img,o), global weights =====
    for (int u = warp; u < 20; u += (TPB / 32)) {
        const int img = u / 10;
        const int o   = u - img * 10;
        const float* y1 = s + SH_IMG0 + img * IMG_STRIDE + PY1;
        const float* wr = fc2_w + o * 50;
        float acc = y1[lane] * wr[lane];
        const int q = lane + 32;
        if (q < 50) acc = fmaf(y1[q], wr[q], acc);
        #pragma unroll
        for (int off = 16; off > 0; off >>= 1)
            acc += __shfl_xor_sync(0xffffffffu, acc, off);
        if (lane == 0)
            s[SH_IMG0 + img * IMG_STRIDE + PLG + o] = acc + fc2_b[o];
    }
    __syncthreads();
    if (tid < 2) {
        const float* lg = s + SH_IMG0 + tid * IMG_STRIDE + PLG;
        float mx = lg[0];
        #pragma unroll
        for (int q = 1; q < 10; q++) mx = fmaxf(mx, lg[q]);
        float sum = 0.0f;
        #pragma unroll
        for (int q = 0; q < 10; q++) sum += expf(lg[q] - mx);
        s[SH_IMG0 + tid * IMG_STRIDE + PLG + 12] = mx + logf(sum);
    }
    __syncthreads();
    if (tid < 20) {
        const int img = tid / 10;
        const int o   = tid - img * 10;
        if (i0 + img < N) {
            const float* lg = s + SH_IMG0 + img * IMG_STRIDE + PLG;
            out[(i0 + img) * 10 + o] = lg[o] - lg[12];
        }
    }
}

extern "C" void kernel_launch(void* const* d_in, const int* in_sizes, int n_in,
                              void* d_out, int out_size) {
    const float* x        = (const float*)d_in[0];
    const float* kf_w1    = (const float*)d_in[1];
    const float* kf_b1    = (const float*)d_in[2];
    const float* kf_w2    = (const float*)d_in[3];
    const float* kf_b2    = (const float*)d_in[4];
    const float* kf_fc1_w = (const float*)d_in[5];
    const float* kf_fc1_b = (const float*)d_in[6];
    const float* kf_fc2_w = (const float*)d_in[7];
    const float* kf_fc2_b = (const float*)d_in[8];
    const float* conv2_w  = (const float*)d_in[9];
    const float* conv2_b  = (const float*)d_in[10];
    const float* fc1_w    = (const float*)d_in[11];
    const float* fc1_b    = (const float*)d_in[12];
    const float* fc2_w    = (const float*)d_in[13];
    const float* fc2_b    = (const float*)d_in[14];
    float* out = (float*)d_out;

    const int N = in_sizes[0] / 784;
    const int grid = (N + 1) / 2;
    cudaFuncSetAttribute(fused_net_kernel,
                         cudaFuncAttributeMaxDynamicSharedMemorySize, SMEM_BYTES);
    fused_net_kernel<<<grid, TPB, SMEM_BYTES>>>(x, kf_w1, kf_b1, kf_w2, kf_b2,
                                                kf_fc1_w, kf_fc1_b, kf_fc2_w, kf_fc2_b,
                                                conv2_w, conv2_b, fc1_w, fc1_b,
                                                fc2_w, fc2_b, out, N);
}

// round 10
// speedup vs baseline: 1.0494x; 1.0494x over previous
#include <cuda_runtime.h>
#include <math.h>

#define TPB 320
typedef unsigned long long u64;

// ---- packed fp32x2 helpers (sm_103a) ----
__device__ __forceinline__ u64 packdup(float a) {
    u64 r; asm("mov.b64 %0,{%1,%1};" : "=l"(r) : "f"(a)); return r;
}
__device__ __forceinline__ u64 fma2(u64 a, u64 b, u64 c) {
    u64 d; asm("fma.rn.f32x2 %0,%1,%2,%3;" : "=l"(d) : "l"(a), "l"(b), "l"(c)); return d;
}
__device__ __forceinline__ void unpk(u64 x, float& lo, float& hi) {
    asm("mov.b64 {%0,%1},%2;" : "=f"(lo), "=f"(hi) : "l"(x));
}

// ---- shared memory layout (floats) ---- (same as R8 best)
#define OFF_W1P 0        // [4 pair][49] x2       (392)
#define OFF_W2P 392      // [5 pair][8ci][25] x2  (2000)
#define OFF_CWP 2392     // [10 pair][10ci][25]x2 (5000)
#define OFF_B1P 7392     // (8)
#define OFF_B2P 7400     // (10)
#define OFF_CBP 7410     // (20) -> 7430 pad 7432
// per-image blocks (x2)
#define SH_IMG0 7432
#define IMG_STRIDE 3176
#define PX   0                // [28][28] (784)
#define PBUF 784              // pooled1 [8][11][12]=1056 / pooled3 [10][13][14]=1820
#define PF   2604             // (90)
#define PH   2694             // (32)
#define PK   2726             // (40) -> 2766 pad 2768
#define PP4  2768             // [20][4][4] (320)
#define PY1  3088             // (64)
#define PLG  3152             // (16) -> 3168
#define SMEM_FLOATS (SH_IMG0 + 2 * IMG_STRIDE)
#define SMEM_BYTES  (SMEM_FLOATS * 4)

__global__ __launch_bounds__(TPB, 4) void fused_net_kernel(
    const float* __restrict__ x,
    const float* __restrict__ kf_w1, const float* __restrict__ kf_b1,
    const float* __restrict__ kf_w2, const float* __restrict__ kf_b2,
    const float* __restrict__ kf_fc1_w, const float* __restrict__ kf_fc1_b,
    const float* __restrict__ kf_fc2_w, const float* __restrict__ kf_fc2_b,
    const float* __restrict__ conv2_w, const float* __restrict__ conv2_b,
    const float* __restrict__ fc1_w, const float* __restrict__ fc1_b,
    const float* __restrict__ fc2_w, const float* __restrict__ fc2_b,
    float* __restrict__ out, int N)
{
    extern __shared__ __align__(16) float s[];

    const int bn  = blockIdx.x;
    const int tid = threadIdx.x;
    const int i0  = 2 * bn;
    const int warp = tid >> 5;
    const int lane = tid & 31;

    // ================= Stage 0: stage inputs into smem =================
    {
        #pragma unroll
        for (int img = 0; img < 2; img++) {
            if (i0 + img < N) {
                const float4* x4 = (const float4*)(x + (i0 + img) * 784);
                float4* sx4 = (float4*)(s + SH_IMG0 + img * IMG_STRIDE + PX);
                for (int i = tid; i < 196; i += TPB) sx4[i] = x4[i];
            }
        }
        for (int i = tid; i < 392; i += TPB) {
            int c = i / 49, q = i - c * 49;
            s[OFF_W1P + (((c >> 1) * 49 + q) << 1) + (c & 1)] = kf_w1[i];
        }
        for (int i = tid; i < 2000; i += TPB) {
            int c = i / 200, r = i - c * 200;
            s[OFF_W2P + (((c >> 1) * 200 + r) << 1) + (c & 1)] = kf_w2[i];
        }
        for (int i = tid; i < 5000; i += TPB) {
            int c = i / 250, r = i - c * 250;
            s[OFF_CWP + (((c >> 1) * 250 + r) << 1) + (c & 1)] = conv2_w[i];
        }
        if (tid < 8)  s[OFF_B1P + tid] = kf_b1[tid];
        if (tid < 10) s[OFF_B2P + tid] = kf_b2[tid];
        if (tid < 20) s[OFF_CBP + tid] = conv2_b[tid];
    }
    __syncthreads();

    // ===== Stage 1: conv7x7 (1->8) + pool + relu -> pooled1 [8][11][12pad] =====
    // weight-row rotation: w[] holds row r-1 at loop entry of iteration r.
    for (int u = tid; u < 968; u += TPB) {
        const int img = u / 484;
        const int t   = u - img * 484;
        const int cp  = t / 121;
        const int r2  = t - cp * 121;
        const int pi  = r2 / 11;
        const int pj  = r2 - pi * 11;
        const float* sx = s + SH_IMG0 + img * IMG_STRIDE + PX;
        const u64* wp = (const u64*)(s + OFF_W1P) + cp * 49;
        const u64 bias = ((const u64*)(s + OFF_B1P))[cp];
        u64 a00 = bias, a01 = bias, a10 = bias, a11 = bias;
        u64 w[7];
        #pragma unroll
        for (int r = 0; r < 8; r++) {
            const float2* row = (const float2*)(sx + (2 * pi + r) * 28 + 2 * pj);
            u64 pd[8];
            #pragma unroll
            for (int j = 0; j < 4; j++) {
                float2 f = row[j];
                pd[2 * j]     = packdup(f.x);
                pd[2 * j + 1] = packdup(f.y);
            }
            if (r >= 1) {      // use w = weight row r-1 for window-row 1
                #pragma unroll
                for (int v = 0; v < 7; v++) {
                    a10 = fma2(pd[v],     w[v], a10);
                    a11 = fma2(pd[v + 1], w[v], a11);
                }
            }
            if (r < 7) {       // load weight row r, use for window-row 0
                #pragma unroll
                for (int v = 0; v < 7; v++) {
                    w[v] = wp[r * 7 + v];
                    a00 = fma2(pd[v],     w[v], a00);
                    a01 = fma2(pd[v + 1], w[v], a01);
                }
            }
        }
        float p0, p1, q0, q1, r0, r1, t0, t1;
        unpk(a00, p0, p1); unpk(a01, q0, q1); unpk(a10, r0, r1); unpk(a11, t0, t1);
        float m0 = fmaxf(fmaxf(p0, q0), fmaxf(r0, t0));
        float m1 = fmaxf(fmaxf(p1, q1), fmaxf(r1, t1));
        float* buf = s + SH_IMG0 + img * IMG_STRIDE + PBUF;
        buf[(2 * cp)     * 132 + pi * 12 + pj] = fmaxf(m0, 0.0f);
        buf[(2 * cp + 1) * 132 + pi * 12 + pj] = fmaxf(m1, 0.0f);
    }
    __syncthreads();

    // ===== Stage 2: conv5x5 (8->10) + pool + relu -> f [10][3][3] =====
    if (tid < 192) {
        const int uu   = tid >> 1;
        const int half = tid & 1;
        const bool valid = uu < 90;
        const int u   = valid ? uu : 0;
        const int img = u / 45;
        const int t   = u - img * 45;
        const int cp  = t / 9;
        const int pos = t - cp * 9;
        const int pi  = pos / 3;
        const int pj  = pos - pi * 3;
        const float* buf = s + SH_IMG0 + img * IMG_STRIDE + PBUF;
        const u64 bias = ((const u64*)(s + OFF_B2P))[cp];
        u64 A[4];
        #pragma unroll
        for (int k = 0; k < 4; k++) A[k] = half ? 0ull : bias;
        u64 w[5];
        #pragma unroll
        for (int cc = 0; cc < 4; cc++) {
            const int ci = 4 * half + cc;
            const u64* wp = (const u64*)(s + OFF_W2P) + (cp * 8 + ci) * 25;
            #pragma unroll
            for (int r = 0; r < 6; r++) {
                const float2* row = (const float2*)(buf + ci * 132 + (2 * pi + r) * 12 + 2 * pj);
                u64 pd[6];
                #pragma unroll
                for (int j = 0; j < 3; j++) {
                    float2 f = row[j];
                    pd[2 * j]     = packdup(f.x);
                    pd[2 * j + 1] = packdup(f.y);
                }
                if (r >= 1) {
                    #pragma unroll
                    for (int v = 0; v < 5; v++) {
                        A[2] = fma2(pd[v],     w[v], A[2]);
                        A[3] = fma2(pd[v + 1], w[v], A[3]);
                    }
                }
                if (r < 5) {
                    #pragma unroll
                    for (int v = 0; v < 5; v++) {
                        w[v] = wp[r * 5 + v];
                        A[0] = fma2(pd[v],     w[v], A[0]);
                        A[1] = fma2(pd[v + 1], w[v], A[1]);
                    }
                }
            }
        }
        float me = -INFINITY, mo = -INFINITY;
        #pragma unroll
        for (int k = 0; k < 4; k++) {
            float lo, hi;
            unpk(A[k], lo, hi);
            lo += __shfl_xor_sync(0xffffffffu, lo, 1);
            hi += __shfl_xor_sync(0xffffffffu, hi, 1);
            me = fmaxf(me, lo);
            mo = fmaxf(mo, hi);
        }
        if (valid) {
            float* f = s + SH_IMG0 + img * IMG_STRIDE + PF;
            if (half == 0) f[(2 * cp)     * 9 + pos] = fmaxf(me, 0.0f);
            else           f[(2 * cp + 1) * 9 + pos] = fmaxf(mo, 0.0f);
        }
    }
    __syncthreads();

    // ===== Stage 3a: hypernet fc1 90->32 relu — warp per output, global weights =====
    for (int u = warp; u < 64; u += (TPB / 32)) {
        const int img = u >> 5;
        const int o   = u & 31;
        const float* f  = s + SH_IMG0 + img * IMG_STRIDE + PF;
        const float* wr = kf_fc1_w + o * 90;
        float acc = 0.0f;
        #pragma unroll
        for (int k = 0; k < 3; k++) {
            const int q = lane + 32 * k;
            if (q < 90) acc = fmaf(f[q], wr[q], acc);
        }
        #pragma unroll
        for (int off = 16; off > 0; off >>= 1)
            acc += __shfl_xor_sync(0xffffffffu, acc, off);
        if (lane == 0)
            s[SH_IMG0 + img * IMG_STRIDE + PH + o] = fmaxf(acc + kf_fc1_b[o], 0.0f);
    }
    __syncthreads();

    // ===== Stage 3b: hypernet fc2 32->40 — warp per output, global weights =====
    for (int u = warp; u < 80; u += (TPB / 32)) {
        const int img = u / 40;
        const int o   = u - img * 40;
        const float* h = s + SH_IMG0 + img * IMG_STRIDE + PH;
        float acc = h[lane] * kf_fc2_w[o * 32 + lane];
        #pragma unroll
        for (int off = 16; off > 0; off >>= 1)
            acc += __shfl_xor_sync(0xffffffffu, acc, off);
        if (lane == 0)
            s[SH_IMG0 + img * IMG_STRIDE + PK + o] = acc + kf_fc2_b[o];
    }
    __syncthreads();

    // ===== Stage 4: dynamic 2x2 conv + pool + relu -> pooled3 [10][13][14pad] =====
    for (int it = tid; it < 3380; it += TPB) {
        const int img = it / 1690;
        const int t   = it - img * 1690;
        const int c   = t / 169;
        const int rem = t - c * 169;
        const int pi  = rem / 13;
        const int pj  = rem - pi * 13;
        const float* base = s + SH_IMG0 + img * IMG_STRIDE;
        const float k00 = base[PK + c * 4 + 0];
        const float k01 = base[PK + c * 4 + 1];
        const float k10 = base[PK + c * 4 + 2];
        const float k11 = base[PK + c * 4 + 3];
        float a[3][3];
        #pragma unroll
        for (int u2 = 0; u2 < 3; u2++) {
            const float2 f01 = *(const float2*)(base + PX + (2 * pi + u2) * 28 + 2 * pj);
            a[u2][0] = f01.x; a[u2][1] = f01.y;
            a[u2][2] = base[PX + (2 * pi + u2) * 28 + 2 * pj + 2];
        }
        float m = -INFINITY;
        #pragma unroll
        for (int di = 0; di < 2; di++)
            #pragma unroll
            for (int dj = 0; dj < 2; dj++) {
                float cv = a[di][dj] * k00;
                cv = fmaf(a[di][dj + 1],     k01, cv);
                cv = fmaf(a[di + 1][dj],     k10, cv);
                cv = fmaf(a[di + 1][dj + 1], k11, cv);
                m = fmaxf(m, cv);
            }
        s[SH_IMG0 + img * IMG_STRIDE + PBUF + c * 182 + pi * 14 + pj] = fmaxf(m, 0.0f);
    }
    __syncthreads();

    // ===== Stage 5: conv5x5 (10->20) + pool + relu -> pooled4 [20][4][4] =====
    if (tid < 320) {
        const int img = tid / 160;
        const int t   = tid - img * 160;
        const int cp  = t / 16;
        const int pos = t - cp * 16;
        const int pi  = pos / 4;
        const int pj  = pos - pi * 4;
        const float* buf = s + SH_IMG0 + img * IMG_STRIDE + PBUF;
        const u64 bias = ((const u64*)(s + OFF_CBP))[cp];
        u64 A[4] = {bias, bias, bias, bias};
        u64 w[5];
        #pragma unroll 2
        for (int ci = 0; ci < 10; ci++) {
            const u64* wp = (const u64*)(s + OFF_CWP) + (cp * 10 + ci) * 25;
            #pragma unroll
            for (int r = 0; r < 6; r++) {
                const float2* row = (const float2*)(buf + ci * 182 + (2 * pi + r) * 14 + 2 * pj);
                u64 pd[6];
                #pragma unroll
                for (int j = 0; j < 3; j++) {
                    float2 f = row[j];
                    pd[2 * j]     = packdup(f.x);
                    pd[2 * j + 1] = packdup(f.y);
                }
                if (r >= 1) {
                    #pragma unroll
                    for (int v = 0; v < 5; v++) {
                        A[2] = fma2(pd[v],     w[v], A[2]);
                        A[3] = fma2(pd[v + 1], w[v], A[3]);
                    }
                }
                if (r < 5) {
                    #pragma unroll
                    for (int v = 0; v < 5; v++) {
                        w[v] = wp[r * 5 + v];
                        A[0] = fma2(pd[v],     w[v], A[0]);
                        A[1] = fma2(pd[v + 1], w[v], A[1]);
                    }
                }
            }
        }
        float p0, p1, q0, q1, r0, r1, t0, t1;
        unpk(A[0], p0, p1); unpk(A[1], q0, q1); unpk(A[2], r0, r1); unpk(A[3], t0, t1);
        float m0 = fmaxf(fmaxf(p0, q0), fmaxf(r0, t0));
        float m1 = fmaxf(fmaxf(p1, q1), fmaxf(r1, t1));
        float* p4 = s + SH_IMG0 + img * IMG_STRIDE + PP4;
        p4[(2 * cp)     * 16 + pos] = fmaxf(m0, 0.0f);
        p4[(2 * cp + 1) * 16 + pos] = fmaxf(m1, 0.0f);
    }
    __syncthreads();

    // ===== Stage 6: fc1 320->50 relu, warp per (img,o), global weights =====
    for (int u = warp; u < 100; u += (TPB / 32)) {
        const int img = u / 50;
        const int o   = u - img * 50;
        const float4* wr = (const float4*)(fc1_w + o * 320);
        const float4* pr = (const float4*)(s + SH_IMG0 + img * IMG_STRIDE + PP4);
        float acc = 0.0f;
        #pragma unroll
        for (int k = 0; k < 3; k++) {
            const int i = lane + 32 * k;
            if (i < 80) {
                float4 w4 = wr[i];
                float4 p4 = pr[i];
                acc = fmaf(w4.x, p4.x, fmaf(w4.y, p4.y,
                      fmaf(w4.z, p4.z, fmaf(w4.w, p4.w, acc))));
            }
        }
        #pragma unroll
        for (int off = 16; off > 0; off >>= 1)
            acc += __shfl_xor_sync(0xffffffffu, acc, off);
        if (lane == 0)
            s[SH_IMG0 + img * IMG_STRIDE + PY1 + o] = fmaxf(acc + fc1_b[o], 0.0f);
    }
    __syncthreads();

    // ===== Stage 7: fc2 50->10 — warp per (img,o), global weights =====
    for (int u = warp; u < 20; u += (TPB / 32)) {
        const int img = u / 10;
        const int o   = u - img * 10;
        const float* y1 = s + SH_IMG0 + img * IMG_STRIDE + PY1;
        const float* wr = fc2_w + o * 50;
        float acc = y1[lane] * wr[lane];
        const int q = lane + 32;
        if (q < 50) acc = fmaf(y1[q], wr[q], acc);
        #pragma unroll
        for (int off = 16; off > 0; off >>= 1)
            acc += __shfl_xor_sync(0xffffffffu, acc, off);
        if (lane == 0)
            s[SH_IMG0 + img * IMG_STRIDE + PLG + o] = acc + fc2_b[o];
    }
    __syncthreads();
    if (tid < 2) {
        const float* lg = s + SH_IMG0 + tid * IMG_STRIDE + PLG;
        float mx = lg[0];
        #pragma unroll
        for (int q = 1; q < 10; q++) mx = fmaxf(mx, lg[q]);
        float sum = 0.0f;
        #pragma unroll
        for (int q = 0; q < 10; q++) sum += expf(lg[q] - mx);
        s[SH_IMG0 + tid * IMG_STRIDE + PLG + 12] = mx + logf(sum);
    }
    __syncthreads();
    if (tid < 20) {
        const int img = tid / 10;
        const int o   = tid - img * 10;
        if (i0 + img < N) {
            const float* lg = s + SH_IMG0 + img * IMG_STRIDE + PLG;
            out[(i0 + img) * 10 + o] = lg[o] - lg[12];
        }
    }
}

extern "C" void kernel_launch(void* const* d_in, const int* in_sizes, int n_in,
                              void* d_out, int out_size) {
    const float* x        = (const float*)d_in[0];
    const float* kf_w1    = (const float*)d_in[1];
    const float* kf_b1    = (const float*)d_in[2];
    const float* kf_w2    = (const float*)d_in[3];
    const float* kf_b2    = (const float*)d_in[4];
    const float* kf_fc1_w = (const float*)d_in[5];
    const float* kf_fc1_b = (const float*)d_in[6];
    const float* kf_fc2_w = (const float*)d_in[7];
    const float* kf_fc2_b = (const float*)d_in[8];
    const float* conv2_w  = (const float*)d_in[9];
    const float* conv2_b  = (const float*)d_in[10];
    const float* fc1_w    = (const float*)d_in[11];
    const float* fc1_b    = (const float*)d_in[12];
    const float* fc2_w    = (const float*)d_in[13];
    const float* fc2_b    = (const float*)d_in[14];
    float* out = (float*)d_out;

    const int N = in_sizes[0] / 784;
    const int grid = (N + 1) / 2;
    cudaFuncSetAttribute(fused_net_kernel,
                         cudaFuncAttributeMaxDynamicSharedMemorySize, SMEM_BYTES);
    fused_net_kernel<<<grid, TPB, SMEM_BYTES>>>(x, kf_w1, kf_b1, kf_w2, kf_b2,
                                                kf_fc1_w, kf_fc1_b, kf_fc2_w, kf_fc2_b,
                                                conv2_w, conv2_b, fc1_w, fc1_b,
                                                fc2_w, fc2_b, out, N);
}

// round 11
// speedup vs baseline: 1.1959x; 1.1397x over previous
#include <cuda_runtime.h>
#include <math.h>

#define TPB 320
typedef unsigned long long u64;

// ---- packed fp32x2 helpers (sm_103a) ----
__device__ __forceinline__ u64 packdup(float a) {
    u64 r; asm("mov.b64 %0,{%1,%1};" : "=l"(r) : "f"(a)); return r;
}
__device__ __forceinline__ u64 fma2(u64 a, u64 b, u64 c) {
    u64 d; asm("fma.rn.f32x2 %0,%1,%2,%3;" : "=l"(d) : "l"(a), "l"(b), "l"(c)); return d;
}
__device__ __forceinline__ void unpk(u64 x, float& lo, float& hi) {
    asm("mov.b64 {%0,%1},%2;" : "=f"(lo), "=f"(hi) : "l"(x));
}

// ---- shared memory layout (floats) ----
#define OFF_W1Q 0        // ull2[2cpq][49 tap] : [pair0(2ch), pair1(2ch)]   (392)
#define OFF_W2P 392      // [5 pair][8ci][25] x2                            (2000)
#define OFF_CWQ 2392     // ull2[5cpq][10ci][25 tap]                        (5000)
#define OFF_B1P 7392     // (8)
#define OFF_B2P 7400     // (10)
#define OFF_CBP 7410     // (20) -> 7430 pad 7432
// per-image blocks (x2)
#define SH_IMG0 7432
#define IMG_STRIDE 2768
#define PX   0                // [28][28] (784); dead after S4 -> aliased below
#define PBUF 784              // pooled1 [8][11][12]=1056 / pooled3 [10][13][14]=1820
#define PF   2604             // (90)
#define PH   2694             // (32)
#define PK   2726             // (40) -> 2766 pad 2768
#define PP4  0                // [20][4][4] (320)  -- aliases PX (dead)
#define PY1  320              // (64)              -- aliases PX
#define PLG  384              // (16)              -- aliases PX
#define SMEM_FLOATS (SH_IMG0 + 2 * IMG_STRIDE)
#define SMEM_BYTES  (SMEM_FLOATS * 4)

__global__ __launch_bounds__(TPB, 3) void fused_net_kernel(
    const float* __restrict__ x,
    const float* __restrict__ kf_w1, const float* __restrict__ kf_b1,
    const float* __restrict__ kf_w2, const float* __restrict__ kf_b2,
    const float* __restrict__ kf_fc1_w, const float* __restrict__ kf_fc1_b,
    const float* __restrict__ kf_fc2_w, const float* __restrict__ kf_fc2_b,
    const float* __restrict__ conv2_w, const float* __restrict__ conv2_b,
    const float* __restrict__ fc1_w, const float* __restrict__ fc1_b,
    const float* __restrict__ fc2_w, const float* __restrict__ fc2_b,
    float* __restrict__ out, int N)
{
    extern __shared__ __align__(16) float s[];

    const int bn  = blockIdx.x;
    const int tid = threadIdx.x;
    const int i0  = 2 * bn;
    const int warp = tid >> 5;
    const int lane = tid & 31;

    // ================= Stage 0: stage inputs into smem =================
    {
        #pragma unroll
        for (int img = 0; img < 2; img++) {
            if (i0 + img < N) {
                const float4* x4 = (const float4*)(x + (i0 + img) * 784);
                float4* sx4 = (float4*)(s + SH_IMG0 + img * IMG_STRIDE + PX);
                for (int i = tid; i < 196; i += TPB) sx4[i] = x4[i];
            }
        }
        // kf_w1 -> ull2[cpq][49]: ((cpq*49+q)*2 + pr)*2 + ch
        for (int i = tid; i < 392; i += TPB) {
            int c = i / 49, q = i - c * 49;
            int cpq = c >> 2, pr = (c >> 1) & 1, ch = c & 1;
            s[OFF_W1Q + ((cpq * 49 + q) * 2 + pr) * 2 + ch] = kf_w1[i];
        }
        // kf_w2 -> [5cp][8ci][25] x2
        for (int i = tid; i < 2000; i += TPB) {
            int c = i / 200, r = i - c * 200;
            s[OFF_W2P + (((c >> 1) * 200 + r) << 1) + (c & 1)] = kf_w2[i];
        }
        // conv2_w -> ull2[cpq][ci][25]: (((cpq*10+ci)*25+q)*2 + pr)*2 + ch
        for (int i = tid; i < 5000; i += TPB) {
            int c = i / 250, r250 = i - c * 250;
            int ci = r250 / 25, q = r250 - ci * 25;
            int cpq = c >> 2, pr = (c >> 1) & 1, ch = c & 1;
            s[OFF_CWQ + (((cpq * 10 + ci) * 25 + q) * 2 + pr) * 2 + ch] = conv2_w[i];
        }
        if (tid < 8)  s[OFF_B1P + tid] = kf_b1[tid];
        if (tid < 10) s[OFF_B2P + tid] = kf_b2[tid];
        if (tid < 20) s[OFF_CBP + tid] = conv2_b[tid];
    }
    __syncthreads();

    // ===== Stage 1: conv7x7 (1->8) + pool + relu -> pooled1 [8][11][12pad] =====
    // unit = (cpq, img, pos). 484 units, 4 out channels per thread (2 f32x2 pairs).
    for (int u = tid; u < 484; u += TPB) {
        const int cpq = u / 242;
        const int rem = u - cpq * 242;
        const int img = rem / 121;
        const int pos = rem - img * 121;
        const int pi  = pos / 11;
        const int pj  = pos - pi * 11;
        const float* sx = s + SH_IMG0 + img * IMG_STRIDE + PX;
        const ulonglong2* wq = (const ulonglong2*)(s + OFF_W1Q) + cpq * 49;
        const u64 b0 = ((const u64*)(s + OFF_B1P))[2 * cpq];
        const u64 b1 = ((const u64*)(s + OFF_B1P))[2 * cpq + 1];
        u64 A0[4] = {b0, b0, b0, b0};
        u64 A1[4] = {b1, b1, b1, b1};
        #pragma unroll
        for (int r = 0; r < 8; r++) {
            const float2* row = (const float2*)(sx + (2 * pi + r) * 28 + 2 * pj);
            u64 pd[8];
            #pragma unroll
            for (int j = 0; j < 4; j++) {
                float2 f = row[j];
                pd[2 * j]     = packdup(f.x);
                pd[2 * j + 1] = packdup(f.y);
            }
            if (r < 7) {
                #pragma unroll
                for (int v = 0; v < 7; v++) {
                    const ulonglong2 w = wq[r * 7 + v];
                    A0[0] = fma2(pd[v],     w.x, A0[0]);
                    A0[1] = fma2(pd[v + 1], w.x, A0[1]);
                    A1[0] = fma2(pd[v],     w.y, A1[0]);
                    A1[1] = fma2(pd[v + 1], w.y, A1[1]);
                }
            }
            if (r >= 1) {
                #pragma unroll
                for (int v = 0; v < 7; v++) {
                    const ulonglong2 w = wq[(r - 1) * 7 + v];
                    A0[2] = fma2(pd[v],     w.x, A0[2]);
                    A0[3] = fma2(pd[v + 1], w.x, A0[3]);
                    A1[2] = fma2(pd[v],     w.y, A1[2]);
                    A1[3] = fma2(pd[v + 1], w.y, A1[3]);
                }
            }
        }
        float* buf = s + SH_IMG0 + img * IMG_STRIDE + PBUF;
        {
            float p0, p1, q0, q1, r0, r1, t0, t1;
            unpk(A0[0], p0, p1); unpk(A0[1], q0, q1); unpk(A0[2], r0, r1); unpk(A0[3], t0, t1);
            buf[(4 * cpq)     * 132 + pi * 12 + pj] =
                fmaxf(fmaxf(fmaxf(p0, q0), fmaxf(r0, t0)), 0.0f);
            buf[(4 * cpq + 1) * 132 + pi * 12 + pj] =
                fmaxf(fmaxf(fmaxf(p1, q1), fmaxf(r1, t1)), 0.0f);
            unpk(A1[0], p0, p1); unpk(A1[1], q0, q1); unpk(A1[2], r0, r1); unpk(A1[3], t0, t1);
            buf[(4 * cpq + 2) * 132 + pi * 12 + pj] =
                fmaxf(fmaxf(fmaxf(p0, q0), fmaxf(r0, t0)), 0.0f);
            buf[(4 * cpq + 3) * 132 + pi * 12 + pj] =
                fmaxf(fmaxf(fmaxf(p1, q1), fmaxf(r1, t1)), 0.0f);
        }
    }
    __syncthreads();

    // ===== Stage 2: conv5x5 (8->10) + pool + relu -> f [10][3][3] =====
    // thread = (unit, ci-half); shfl_xor(1) combine; weight-row rotation.
    if (tid < 192) {
        const int uu   = tid >> 1;
        const int half = tid & 1;
        const bool valid = uu < 90;
        const int u   = valid ? uu : 0;
        const int img = u / 45;
        const int t   = u - img * 45;
        const int cp  = t / 9;
        const int pos = t - cp * 9;
        const int pi  = pos / 3;
        const int pj  = pos - pi * 3;
        const float* buf = s + SH_IMG0 + img * IMG_STRIDE + PBUF;
        const u64 bias = ((const u64*)(s + OFF_B2P))[cp];
        u64 A[4];
        #pragma unroll
        for (int k = 0; k < 4; k++) A[k] = half ? 0ull : bias;
        u64 w[5];
        #pragma unroll
        for (int cc = 0; cc < 4; cc++) {
            const int ci = 4 * half + cc;
            const u64* wp = (const u64*)(s + OFF_W2P) + (cp * 8 + ci) * 25;
            #pragma unroll
            for (int r = 0; r < 6; r++) {
                const float2* row = (const float2*)(buf + ci * 132 + (2 * pi + r) * 12 + 2 * pj);
                u64 pd[6];
                #pragma unroll
                for (int j = 0; j < 3; j++) {
                    float2 f = row[j];
                    pd[2 * j]     = packdup(f.x);
                    pd[2 * j + 1] = packdup(f.y);
                }
                if (r >= 1) {
                    #pragma unroll
                    for (int v = 0; v < 5; v++) {
                        A[2] = fma2(pd[v],     w[v], A[2]);
                        A[3] = fma2(pd[v + 1], w[v], A[3]);
                    }
                }
                if (r < 5) {
                    #pragma unroll
                    for (int v = 0; v < 5; v++) {
                        w[v] = wp[r * 5 + v];
                        A[0] = fma2(pd[v],     w[v], A[0]);
                        A[1] = fma2(pd[v + 1], w[v], A[1]);
                    }
                }
            }
        }
        float me = -INFINITY, mo = -INFINITY;
        #pragma unroll
        for (int k = 0; k < 4; k++) {
            float lo, hi;
            unpk(A[k], lo, hi);
            lo += __shfl_xor_sync(0xffffffffu, lo, 1);
            hi += __shfl_xor_sync(0xffffffffu, hi, 1);
            me = fmaxf(me, lo);
            mo = fmaxf(mo, hi);
        }
        if (valid) {
            float* f = s + SH_IMG0 + img * IMG_STRIDE + PF;
            if (half == 0) f[(2 * cp)     * 9 + pos] = fmaxf(me, 0.0f);
            else           f[(2 * cp + 1) * 9 + pos] = fmaxf(mo, 0.0f);
        }
    }
    __syncthreads();

    // ===== Stage 3a: hypernet fc1 90->32 relu — warp per output, global weights =====
    for (int u = warp; u < 64; u += (TPB / 32)) {
        const int img = u >> 5;
        const int o   = u & 31;
        const float* f  = s + SH_IMG0 + img * IMG_STRIDE + PF;
        const float* wr = kf_fc1_w + o * 90;
        float acc = 0.0f;
        #pragma unroll
        for (int k = 0; k < 3; k++) {
            const int q = lane + 32 * k;
            if (q < 90) acc = fmaf(f[q], wr[q], acc);
        }
        #pragma unroll
        for (int off = 16; off > 0; off >>= 1)
            acc += __shfl_xor_sync(0xffffffffu, acc, off);
        if (lane == 0)
            s[SH_IMG0 + img * IMG_STRIDE + PH + o] = fmaxf(acc + kf_fc1_b[o], 0.0f);
    }
    __syncthreads();

    // ===== Stage 3b: hypernet fc2 32->40 — warp per output, global weights =====
    for (int u = warp; u < 80; u += (TPB / 32)) {
        const int img = u / 40;
        const int o   = u - img * 40;
        const float* h = s + SH_IMG0 + img * IMG_STRIDE + PH;
        float acc = h[lane] * kf_fc2_w[o * 32 + lane];
        #pragma unroll
        for (int off = 16; off > 0; off >>= 1)
            acc += __shfl_xor_sync(0xffffffffu, acc, off);
        if (lane == 0)
            s[SH_IMG0 + img * IMG_STRIDE + PK + o] = acc + kf_fc2_b[o];
    }
    __syncthreads();

    // ===== Stage 4: dynamic 2x2 conv + pool + relu -> pooled3 [10][13][14pad] =====
    for (int it = tid; it < 3380; it += TPB) {
        const int img = it / 1690;
        const int t   = it - img * 1690;
        const int c   = t / 169;
        const int rem = t - c * 169;
        const int pi  = rem / 13;
        const int pj  = rem - pi * 13;
        const float* base = s + SH_IMG0 + img * IMG_STRIDE;
        const float k00 = base[PK + c * 4 + 0];
        const float k01 = base[PK + c * 4 + 1];
        const float k10 = base[PK + c * 4 + 2];
        const float k11 = base[PK + c * 4 + 3];
        float a[3][3];
        #pragma unroll
        for (int u2 = 0; u2 < 3; u2++) {
            const float2 f01 = *(const float2*)(base + PX + (2 * pi + u2) * 28 + 2 * pj);
            a[u2][0] = f01.x; a[u2][1] = f01.y;
            a[u2][2] = base[PX + (2 * pi + u2) * 28 + 2 * pj + 2];
        }
        float m = -INFINITY;
        #pragma unroll
        for (int di = 0; di < 2; di++)
            #pragma unroll
            for (int dj = 0; dj < 2; dj++) {
                float cv = a[di][dj] * k00;
                cv = fmaf(a[di][dj + 1],     k01, cv);
                cv = fmaf(a[di + 1][dj],     k10, cv);
                cv = fmaf(a[di + 1][dj + 1], k11, cv);
                m = fmaxf(m, cv);
            }
        s[SH_IMG0 + img * IMG_STRIDE + PBUF + c * 182 + pi * 14 + pj] = fmaxf(m, 0.0f);
    }
    __syncthreads();

    // ===== Stage 5: conv5x5 (10->20) + pool + relu -> pooled4 [20][4][4] =====
    // thread = (cpq warp-uniform, img, pos16). 160 units, 4 out channels each,
    // ull2 weight-row rotation.
    if (tid < 160) {
        const int cpq = tid >> 5;            // 0..4, uniform per warp
        const int img = (tid >> 4) & 1;
        const int pos = tid & 15;
        const int pi  = pos >> 2;
        const int pj  = pos & 3;
        const float* buf = s + SH_IMG0 + img * IMG_STRIDE + PBUF;
        const u64 b0 = ((const u64*)(s + OFF_CBP))[2 * cpq];
        const u64 b1 = ((const u64*)(s + OFF_CBP))[2 * cpq + 1];
        u64 A0[4] = {b0, b0, b0, b0};
        u64 A1[4] = {b1, b1, b1, b1};
        ulonglong2 w[5];
        #pragma unroll 2
        for (int ci = 0; ci < 10; ci++) {
            const ulonglong2* wq = (const ulonglong2*)(s + OFF_CWQ) + (cpq * 10 + ci) * 25;
            #pragma unroll
            for (int r = 0; r < 6; r++) {
                const float2* row = (const float2*)(buf + ci * 182 + (2 * pi + r) * 14 + 2 * pj);
                u64 pd[6];
                #pragma unroll
                for (int j = 0; j < 3; j++) {
                    float2 f = row[j];
                    pd[2 * j]     = packdup(f.x);
                    pd[2 * j + 1] = packdup(f.y);
                }
                if (r >= 1) {
                    #pragma unroll
                    for (int v = 0; v < 5; v++) {
                        A0[2] = fma2(pd[v],     w[v].x, A0[2]);
                        A0[3] = fma2(pd[v + 1], w[v].x, A0[3]);
                        A1[2] = fma2(pd[v],     w[v].y, A1[2]);
                        A1[3] = fma2(pd[v + 1], w[v].y, A1[3]);
                    }
                }
                if (r < 5) {
                    #pragma unroll
                    for (int v = 0; v < 5; v++) {
                        w[v] = wq[r * 5 + v];
                        A0[0] = fma2(pd[v],     w[v].x, A0[0]);
                        A0[1] = fma2(pd[v + 1], w[v].x, A0[1]);
                        A1[0] = fma2(pd[v],     w[v].y, A1[0]);
                        A1[1] = fma2(pd[v + 1], w[v].y, A1[1]);
                    }
                }
            }
        }
        float* p4 = s + SH_IMG0 + img * IMG_STRIDE + PP4;
        {
            float p0, p1, q0, q1, r0, r1, t0, t1;
            unpk(A0[0], p0, p1); unpk(A0[1], q0, q1); unpk(A0[2], r0, r1); unpk(A0[3], t0, t1);
            p4[(4 * cpq)     * 16 + pos] = fmaxf(fmaxf(fmaxf(p0, q0), fmaxf(r0, t0)), 0.0f);
            p4[(4 * cpq + 1) * 16 + pos] = fmaxf(fmaxf(fmaxf(p1, q1), fmaxf(r1, t1)), 0.0f);
            unpk(A1[0], p0, p1); unpk(A1[1], q0, q1); unpk(A1[2], r0, r1); unpk(A1[3], t0, t1);
            p4[(4 * cpq + 2) * 16 + pos] = fmaxf(fmaxf(fmaxf(p0, q0), fmaxf(r0, t0)), 0.0f);
            p4[(4 * cpq + 3) * 16 + pos] = fmaxf(fmaxf(fmaxf(p1, q1), fmaxf(r1, t1)), 0.0f);
        }
    }
    __syncthreads();

    // ===== Stage 6: fc1 320->50 relu — warp per o, weights loaded once for BOTH imgs =====
    for (int o = warp; o < 50; o += (TPB / 32)) {
        const float4* wr = (const float4*)(fc1_w + o * 320);
        float4 w4[3];
        #pragma unroll
        for (int k = 0; k < 3; k++) {
            const int i = lane + 32 * k;
            w4[k] = (i < 80) ? wr[i] : make_float4(0.f, 0.f, 0.f, 0.f);
        }
        #pragma unroll
        for (int img = 0; img < 2; img++) {
            const float4* pr = (const float4*)(s + SH_IMG0 + img * IMG_STRIDE + PP4);
            float acc = 0.0f;
            #pragma unroll
            for (int k = 0; k < 3; k++) {
                const int i = lane + 32 * k;
                if (i < 80) {
                    float4 p4 = pr[i];
                    acc = fmaf(w4[k].x, p4.x, fmaf(w4[k].y, p4.y,
                          fmaf(w4[k].z, p4.z, fmaf(w4[k].w, p4.w, acc))));
                }
            }
            #pragma unroll
            for (int off = 16; off > 0; off >>= 1)
                acc += __shfl_xor_sync(0xffffffffu, acc, off);
            if (lane == 0)
                s[SH_IMG0 + img * IMG_STRIDE + PY1 + o] = fmaxf(acc + fc1_b[o], 0.0f);
        }
    }
    __syncthreads();

    // ===== Stage 7: fc2 50->10 — warp per (img,o), global weights =====
    for (int u = warp; u < 20; u += (TPB / 32)) {
        const int img = u / 10;
        const int o   = u - img * 10;
        const float* y1 = s + SH_IMG0 + img * IMG_STRIDE + PY1;
        const float* wr = fc2_w + o * 50;
        float acc = y1[lane] * wr[lane];
        const int q = lane + 32;
        if (q < 50) acc = fmaf(y1[q], wr[q], acc);
        #pragma unroll
        for (int off = 16; off > 0; off >>= 1)
            acc += __shfl_xor_sync(0xffffffffu, acc, off);
        if (lane == 0)
            s[SH_IMG0 + img * IMG_STRIDE + PLG + o] = acc + fc2_b[o];
    }
    __syncthreads();
    if (tid < 2) {
        const float* lg = s + SH_IMG0 + tid * IMG_STRIDE + PLG;
        float mx = lg[0];
        #pragma unroll
        for (int q = 1; q < 10; q++) mx = fmaxf(mx, lg[q]);
        float sum = 0.0f;
        #pragma unroll
        for (int q = 0; q < 10; q++) sum += expf(lg[q] - mx);
        s[SH_IMG0 + tid * IMG_STRIDE + PLG + 12] = mx + logf(sum);
    }
    __syncthreads();
    if (tid < 20) {
        const int img = tid / 10;
        const int o   = tid - img * 10;
        if (i0 + img < N) {
            const float* lg = s + SH_IMG0 + img * IMG_STRIDE + PLG;
            out[(i0 + img) * 10 + o] = lg[o] - lg[12];
        }
    }
}

extern "C" void kernel_launch(void* const* d_in, const int* in_sizes, int n_in,
                              void* d_out, int out_size) {
    const float* x        = (const float*)d_in[0];
    const float* kf_w1    = (const float*)d_in[1];
    const float* kf_b1    = (const float*)d_in[2];
    const float* kf_w2    = (const float*)d_in[3];
    const float* kf_b2    = (const float*)d_in[4];
    const float* kf_fc1_w = (const float*)d_in[5];
    const float* kf_fc1_b = (const float*)d_in[6];
    const float* kf_fc2_w = (const float*)d_in[7];
    const float* kf_fc2_b = (const float*)d_in[8];
    const float* conv2_w  = (const float*)d_in[9];
    const float* conv2_b  = (const float*)d_in[10];
    const float* fc1_w    = (const float*)d_in[11];
    const float* fc1_b    = (const float*)d_in[12];
    const float* fc2_w    = (const float*)d_in[13];
    const float* fc2_b    = (const float*)d_in[14];
    float* out = (float*)d_out;

    const int N = in_sizes[0] / 784;
    const int grid = (N + 1) / 2;
    cudaFuncSetAttribute(fused_net_kernel,
                         cudaFuncAttributeMaxDynamicSharedMemorySize, SMEM_BYTES);
    fused_net_kernel<<<grid, TPB, SMEM_BYTES>>>(x, kf_w1, kf_b1, kf_w2, kf_b2,
                                                kf_fc1_w, kf_fc1_b, kf_fc2_w, kf_fc2_b,
                                                conv2_w, conv2_b, fc1_w, fc1_b,
                                                fc2_w, fc2_b, out, N);
}

// round 12
// speedup vs baseline: 1.2662x; 1.0588x over previous
#include <cuda_runtime.h>
#include <math.h>

#define TPB 320
typedef unsigned long long u64;

// ---- packed fp32x2 helpers (sm_103a) ----
__device__ __forceinline__ u64 packdup(float a) {
    u64 r; asm("mov.b64 %0,{%1,%1};" : "=l"(r) : "f"(a)); return r;
}
__device__ __forceinline__ u64 fma2(u64 a, u64 b, u64 c) {
    u64 d; asm("fma.rn.f32x2 %0,%1,%2,%3;" : "=l"(d) : "l"(a), "l"(b), "l"(c)); return d;
}
__device__ __forceinline__ void unpk(u64 x, float& lo, float& hi) {
    asm("mov.b64 {%0,%1},%2;" : "=f"(lo), "=f"(hi) : "l"(x));
}

// ---- shared memory layout (floats) ----
#define OFF_W1Q 0        // ull2[2cpq][49 tap]                              (392)
#define OFF_W2P 392      // [5 pair][8ci][25] x2                            (2000)
#define OFF_CWQ 2392     // ull2[5cpq][10ci][25 tap]                        (5000)
#define OFF_B1P 7392     // (8)
#define OFF_B2P 7400     // (10)
#define OFF_CBP 7410     // (20) -> 7430 pad 7432
// per-image blocks (x2)
#define SH_IMG0 7432
#define IMG_STRIDE 2768
#define PX   0                // [28][28] (784); dead after S4 -> aliased below
#define PBUF 784              // pooled1 [8][11][12]=1056 / pooled3 [10][13][14]=1820
#define PF   2604             // (90)
#define PH   2694             // (32)
#define PK   2726             // (40) -> 2766 pad 2768
#define PP4  0                // [20][4][4] (320)  -- aliases PX (dead)
#define PY1  320              // (64)              -- aliases PX
#define PLG  384              // (16)              -- aliases PX
#define SMEM_FLOATS (SH_IMG0 + 2 * IMG_STRIDE)
#define SMEM_BYTES  (SMEM_FLOATS * 4)

__global__ __launch_bounds__(TPB, 3) void fused_net_kernel(
    const float* __restrict__ x,
    const float* __restrict__ kf_w1, const float* __restrict__ kf_b1,
    const float* __restrict__ kf_w2, const float* __restrict__ kf_b2,
    const float* __restrict__ kf_fc1_w, const float* __restrict__ kf_fc1_b,
    const float* __restrict__ kf_fc2_w, const float* __restrict__ kf_fc2_b,
    const float* __restrict__ conv2_w, const float* __restrict__ conv2_b,
    const float* __restrict__ fc1_w, const float* __restrict__ fc1_b,
    const float* __restrict__ fc2_w, const float* __restrict__ fc2_b,
    float* __restrict__ out, int N)
{
    extern __shared__ __align__(16) float s[];

    const int bn  = blockIdx.x;
    const int tid = threadIdx.x;
    const int i0  = 2 * bn;
    const int warp = tid >> 5;
    const int lane = tid & 31;

    // ================= Stage 0: stage inputs into smem =================
    {
        #pragma unroll
        for (int img = 0; img < 2; img++) {
            if (i0 + img < N) {
                const float4* x4 = (const float4*)(x + (i0 + img) * 784);
                float4* sx4 = (float4*)(s + SH_IMG0 + img * IMG_STRIDE + PX);
                for (int i = tid; i < 196; i += TPB) sx4[i] = x4[i];
            }
        }
        for (int i = tid; i < 392; i += TPB) {
            int c = i / 49, q = i - c * 49;
            int cpq = c >> 2, pr = (c >> 1) & 1, ch = c & 1;
            s[OFF_W1Q + ((cpq * 49 + q) * 2 + pr) * 2 + ch] = kf_w1[i];
        }
        for (int i = tid; i < 2000; i += TPB) {
            int c = i / 200, r = i - c * 200;
            s[OFF_W2P + (((c >> 1) * 200 + r) << 1) + (c & 1)] = kf_w2[i];
        }
        for (int i = tid; i < 5000; i += TPB) {
            int c = i / 250, r250 = i - c * 250;
            int ci = r250 / 25, q = r250 - ci * 25;
            int cpq = c >> 2, pr = (c >> 1) & 1, ch = c & 1;
            s[OFF_CWQ + (((cpq * 10 + ci) * 25 + q) * 2 + pr) * 2 + ch] = conv2_w[i];
        }
        if (tid < 8)  s[OFF_B1P + tid] = kf_b1[tid];
        if (tid < 10) s[OFF_B2P + tid] = kf_b2[tid];
        if (tid < 20) s[OFF_CBP + tid] = conv2_b[tid];
    }
    __syncthreads();

    // ===== Stage 1: conv7x7 (1->8) + pool + relu -> pooled1 [8][11][12pad] =====
    // unit = (cpq, img, pos). 484 units, 4 out channels per thread.
    for (int u = tid; u < 484; u += TPB) {
        const int cpq = u / 242;
        const int rem = u - cpq * 242;
        const int img = rem / 121;
        const int pos = rem - img * 121;
        const int pi  = pos / 11;
        const int pj  = pos - pi * 11;
        const float* sx = s + SH_IMG0 + img * IMG_STRIDE + PX;
        const ulonglong2* wq = (const ulonglong2*)(s + OFF_W1Q) + cpq * 49;
        const u64 b0 = ((const u64*)(s + OFF_B1P))[2 * cpq];
        const u64 b1 = ((const u64*)(s + OFF_B1P))[2 * cpq + 1];
        u64 A0[4] = {b0, b0, b0, b0};
        u64 A1[4] = {b1, b1, b1, b1};
        #pragma unroll
        for (int r = 0; r < 8; r++) {
            const float2* row = (const float2*)(sx + (2 * pi + r) * 28 + 2 * pj);
            u64 pd[8];
            #pragma unroll
            for (int j = 0; j < 4; j++) {
                float2 f = row[j];
                pd[2 * j]     = packdup(f.x);
                pd[2 * j + 1] = packdup(f.y);
            }
            if (r < 7) {
                #pragma unroll
                for (int v = 0; v < 7; v++) {
                    const ulonglong2 w = wq[r * 7 + v];
                    A0[0] = fma2(pd[v],     w.x, A0[0]);
                    A0[1] = fma2(pd[v + 1], w.x, A0[1]);
                    A1[0] = fma2(pd[v],     w.y, A1[0]);
                    A1[1] = fma2(pd[v + 1], w.y, A1[1]);
                }
            }
            if (r >= 1) {
                #pragma unroll
                for (int v = 0; v < 7; v++) {
                    const ulonglong2 w = wq[(r - 1) * 7 + v];
                    A0[2] = fma2(pd[v],     w.x, A0[2]);
                    A0[3] = fma2(pd[v + 1], w.x, A0[3]);
                    A1[2] = fma2(pd[v],     w.y, A1[2]);
                    A1[3] = fma2(pd[v + 1], w.y, A1[3]);
                }
            }
        }
        float* buf = s + SH_IMG0 + img * IMG_STRIDE + PBUF;
        {
            float p0, p1, q0, q1, r0, r1, t0, t1;
            unpk(A0[0], p0, p1); unpk(A0[1], q0, q1); unpk(A0[2], r0, r1); unpk(A0[3], t0, t1);
            buf[(4 * cpq)     * 132 + pi * 12 + pj] =
                fmaxf(fmaxf(fmaxf(p0, q0), fmaxf(r0, t0)), 0.0f);
            buf[(4 * cpq + 1) * 132 + pi * 12 + pj] =
                fmaxf(fmaxf(fmaxf(p1, q1), fmaxf(r1, t1)), 0.0f);
            unpk(A1[0], p0, p1); unpk(A1[1], q0, q1); unpk(A1[2], r0, r1); unpk(A1[3], t0, t1);
            buf[(4 * cpq + 2) * 132 + pi * 12 + pj] =
                fmaxf(fmaxf(fmaxf(p0, q0), fmaxf(r0, t0)), 0.0f);
            buf[(4 * cpq + 3) * 132 + pi * 12 + pj] =
                fmaxf(fmaxf(fmaxf(p1, q1), fmaxf(r1, t1)), 0.0f);
        }
    }
    __syncthreads();

    // ===== Stage 2: conv5x5 (8->10) + pool + relu -> f [10][3][3] =====
    if (tid < 192) {
        const int uu   = tid >> 1;
        const int half = tid & 1;
        const bool valid = uu < 90;
        const int u   = valid ? uu : 0;
        const int img = u / 45;
        const int t   = u - img * 45;
        const int cp  = t / 9;
        const int pos = t - cp * 9;
        const int pi  = pos / 3;
        const int pj  = pos - pi * 3;
        const float* buf = s + SH_IMG0 + img * IMG_STRIDE + PBUF;
        const u64 bias = ((const u64*)(s + OFF_B2P))[cp];
        u64 A[4];
        #pragma unroll
        for (int k = 0; k < 4; k++) A[k] = half ? 0ull : bias;
        u64 w[5];
        #pragma unroll
        for (int cc = 0; cc < 4; cc++) {
            const int ci = 4 * half + cc;
            const u64* wp = (const u64*)(s + OFF_W2P) + (cp * 8 + ci) * 25;
            #pragma unroll
            for (int r = 0; r < 6; r++) {
                const float2* row = (const float2*)(buf + ci * 132 + (2 * pi + r) * 12 + 2 * pj);
                u64 pd[6];
                #pragma unroll
                for (int j = 0; j < 3; j++) {
                    float2 f = row[j];
                    pd[2 * j]     = packdup(f.x);
                    pd[2 * j + 1] = packdup(f.y);
                }
                if (r >= 1) {
                    #pragma unroll
                    for (int v = 0; v < 5; v++) {
                        A[2] = fma2(pd[v],     w[v], A[2]);
                        A[3] = fma2(pd[v + 1], w[v], A[3]);
                    }
                }
                if (r < 5) {
                    #pragma unroll
                    for (int v = 0; v < 5; v++) {
                        w[v] = wp[r * 5 + v];
                        A[0] = fma2(pd[v],     w[v], A[0]);
                        A[1] = fma2(pd[v + 1], w[v], A[1]);
                    }
                }
            }
        }
        float me = -INFINITY, mo = -INFINITY;
        #pragma unroll
        for (int k = 0; k < 4; k++) {
            float lo, hi;
            unpk(A[k], lo, hi);
            lo += __shfl_xor_sync(0xffffffffu, lo, 1);
            hi += __shfl_xor_sync(0xffffffffu, hi, 1);
            me = fmaxf(me, lo);
            mo = fmaxf(mo, hi);
        }
        if (valid) {
            float* f = s + SH_IMG0 + img * IMG_STRIDE + PF;
            if (half == 0) f[(2 * cp)     * 9 + pos] = fmaxf(me, 0.0f);
            else           f[(2 * cp + 1) * 9 + pos] = fmaxf(mo, 0.0f);
        }
    }
    __syncthreads();

    // ===== Stage 3a: hypernet fc1 90->32 relu =====
    for (int u = warp; u < 64; u += (TPB / 32)) {
        const int img = u >> 5;
        const int o   = u & 31;
        const float* f  = s + SH_IMG0 + img * IMG_STRIDE + PF;
        const float* wr = kf_fc1_w + o * 90;
        float acc = 0.0f;
        #pragma unroll
        for (int k = 0; k < 3; k++) {
            const int q = lane + 32 * k;
            if (q < 90) acc = fmaf(f[q], wr[q], acc);
        }
        #pragma unroll
        for (int off = 16; off > 0; off >>= 1)
            acc += __shfl_xor_sync(0xffffffffu, acc, off);
        if (lane == 0)
            s[SH_IMG0 + img * IMG_STRIDE + PH + o] = fmaxf(acc + kf_fc1_b[o], 0.0f);
    }
    __syncthreads();

    // ===== Stage 3b: hypernet fc2 32->40 =====
    for (int u = warp; u < 80; u += (TPB / 32)) {
        const int img = u / 40;
        const int o   = u - img * 40;
        const float* h = s + SH_IMG0 + img * IMG_STRIDE + PH;
        float acc = h[lane] * kf_fc2_w[o * 32 + lane];
        #pragma unroll
        for (int off = 16; off > 0; off >>= 1)
            acc += __shfl_xor_sync(0xffffffffu, acc, off);
        if (lane == 0)
            s[SH_IMG0 + img * IMG_STRIDE + PK + o] = acc + kf_fc2_b[o];
    }
    __syncthreads();

    // ===== Stage 4: dynamic 2x2 conv + pool + relu -> pooled3 [10][13][14pad] =====
    for (int it = tid; it < 3380; it += TPB) {
        const int img = it / 1690;
        const int t   = it - img * 1690;
        const int c   = t / 169;
        const int rem = t - c * 169;
        const int pi  = rem / 13;
        const int pj  = rem - pi * 13;
        const float* base = s + SH_IMG0 + img * IMG_STRIDE;
        const float k00 = base[PK + c * 4 + 0];
        const float k01 = base[PK + c * 4 + 1];
        const float k10 = base[PK + c * 4 + 2];
        const float k11 = base[PK + c * 4 + 3];
        float a[3][3];
        #pragma unroll
        for (int u2 = 0; u2 < 3; u2++) {
            const float2 f01 = *(const float2*)(base + PX + (2 * pi + u2) * 28 + 2 * pj);
            a[u2][0] = f01.x; a[u2][1] = f01.y;
            a[u2][2] = base[PX + (2 * pi + u2) * 28 + 2 * pj + 2];
        }
        float m = -INFINITY;
        #pragma unroll
        for (int di = 0; di < 2; di++)
            #pragma unroll
            for (int dj = 0; dj < 2; dj++) {
                float cv = a[di][dj] * k00;
                cv = fmaf(a[di][dj + 1],     k01, cv);
                cv = fmaf(a[di + 1][dj],     k10, cv);
                cv = fmaf(a[di + 1][dj + 1], k11, cv);
                m = fmaxf(m, cv);
            }
        s[SH_IMG0 + img * IMG_STRIDE + PBUF + c * 182 + pi * 14 + pj] = fmaxf(m, 0.0f);
    }
    __syncthreads();

    // ===== Stage 5: conv5x5 (10->20) + pool + relu -> pooled4 [20][4][4] =====
    // 320 threads: warp = (cpq, img); lane bit4 = ci-half; lanes 0-15/16-31 same pos.
    // 4 out channels per thread; ci halves combined by shfl_xor(16).
    {
        const int cpq = warp >> 1;           // 0..4, uniform per warp
        const int img = warp & 1;
        const int cih = lane >> 4;           // 0/1
        const int pos = lane & 15;
        const int pi  = pos >> 2;
        const int pj  = pos & 3;
        const float* buf = s + SH_IMG0 + img * IMG_STRIDE + PBUF;
        const u64 b0 = ((const u64*)(s + OFF_CBP))[2 * cpq];
        const u64 b1 = ((const u64*)(s + OFF_CBP))[2 * cpq + 1];
        u64 A0[4], A1[4];
        #pragma unroll
        for (int k = 0; k < 4; k++) {
            A0[k] = cih ? 0ull : b0;
            A1[k] = cih ? 0ull : b1;
        }
        ulonglong2 w[5];
        #pragma unroll
        for (int cc = 0; cc < 5; cc++) {
            const int ci = 5 * cih + cc;
            const ulonglong2* wq = (const ulonglong2*)(s + OFF_CWQ) + (cpq * 10 + ci) * 25;
            #pragma unroll
            for (int r = 0; r < 6; r++) {
                const float2* row = (const float2*)(buf + ci * 182 + (2 * pi + r) * 14 + 2 * pj);
                u64 pd[6];
                #pragma unroll
                for (int j = 0; j < 3; j++) {
                    float2 f = row[j];
                    pd[2 * j]     = packdup(f.x);
                    pd[2 * j + 1] = packdup(f.y);
                }
                if (r >= 1) {
                    #pragma unroll
                    for (int v = 0; v < 5; v++) {
                        A0[2] = fma2(pd[v],     w[v].x, A0[2]);
                        A0[3] = fma2(pd[v + 1], w[v].x, A0[3]);
                        A1[2] = fma2(pd[v],     w[v].y, A1[2]);
                        A1[3] = fma2(pd[v + 1], w[v].y, A1[3]);
                    }
                }
                if (r < 5) {
                    #pragma unroll
                    for (int v = 0; v < 5; v++) {
                        w[v] = wq[r * 5 + v];
                        A0[0] = fma2(pd[v],     w[v].x, A0[0]);
                        A0[1] = fma2(pd[v + 1], w[v].x, A0[1]);
                        A1[0] = fma2(pd[v],     w[v].y, A1[0]);
                        A1[1] = fma2(pd[v + 1], w[v].y, A1[1]);
                    }
                }
            }
        }
        float* p4 = s + SH_IMG0 + img * IMG_STRIDE + PP4;
        {
            float m0 = -INFINITY, m1 = -INFINITY;
            #pragma unroll
            for (int k = 0; k < 4; k++) {
                float lo, hi;
                unpk(A0[k], lo, hi);
                lo += __shfl_xor_sync(0xffffffffu, lo, 16);
                hi += __shfl_xor_sync(0xffffffffu, hi, 16);
                m0 = fmaxf(m0, lo);
                m1 = fmaxf(m1, hi);
            }
            if (cih == 0) {
                p4[(4 * cpq)     * 16 + pos] = fmaxf(m0, 0.0f);
                p4[(4 * cpq + 1) * 16 + pos] = fmaxf(m1, 0.0f);
            }
        }
        {
            float m0 = -INFINITY, m1 = -INFINITY;
            #pragma unroll
            for (int k = 0; k < 4; k++) {
                float lo, hi;
                unpk(A1[k], lo, hi);
                lo += __shfl_xor_sync(0xffffffffu, lo, 16);
                hi += __shfl_xor_sync(0xffffffffu, hi, 16);
                m0 = fmaxf(m0, lo);
                m1 = fmaxf(m1, hi);
            }
            if (cih == 0) {
                p4[(4 * cpq + 2) * 16 + pos] = fmaxf(m0, 0.0f);
                p4[(4 * cpq + 3) * 16 + pos] = fmaxf(m1, 0.0f);
            }
        }
    }
    __syncthreads();

    // ===== Stage 6: fc1 320->50 relu — warp per o, weights loaded once for BOTH imgs =====
    for (int o = warp; o < 50; o += (TPB / 32)) {
        const float4* wr = (const float4*)(fc1_w + o * 320);
        float4 w4[3];
        #pragma unroll
        for (int k = 0; k < 3; k++) {
            const int i = lane + 32 * k;
            w4[k] = (i < 80) ? wr[i] : make_float4(0.f, 0.f, 0.f, 0.f);
        }
        #pragma unroll
        for (int img = 0; img < 2; img++) {
            const float4* pr = (const float4*)(s + SH_IMG0 + img * IMG_STRIDE + PP4);
            float acc = 0.0f;
            #pragma unroll
            for (int k = 0; k < 3; k++) {
                const int i = lane + 32 * k;
                if (i < 80) {
                    float4 p4 = pr[i];
                    acc = fmaf(w4[k].x, p4.x, fmaf(w4[k].y, p4.y,
                          fmaf(w4[k].z, p4.z, fmaf(w4[k].w, p4.w, acc))));
                }
            }
            #pragma unroll
            for (int off = 16; off > 0; off >>= 1)
                acc += __shfl_xor_sync(0xffffffffu, acc, off);
            if (lane == 0)
                s[SH_IMG0 + img * IMG_STRIDE + PY1 + o] = fmaxf(acc + fc1_b[o], 0.0f);
        }
    }
    __syncthreads();

    // ===== Stage 7: fc2 50->10 — warp per (img,o) =====
    for (int u = warp; u < 20; u += (TPB / 32)) {
        const int img = u / 10;
        const int o   = u - img * 10;
        const float* y1 = s + SH_IMG0 + img * IMG_STRIDE + PY1;
        const float* wr = fc2_w + o * 50;
        float acc = y1[lane] * wr[lane];
        const int q = lane + 32;
        if (q < 50) acc = fmaf(y1[q], wr[q], acc);
        #pragma unroll
        for (int off = 16; off > 0; off >>= 1)
            acc += __shfl_xor_sync(0xffffffffu, acc, off);
        if (lane == 0)
            s[SH_IMG0 + img * IMG_STRIDE + PLG + o] = acc + fc2_b[o];
    }
    __syncthreads();
    if (tid < 2) {
        const float* lg = s + SH_IMG0 + tid * IMG_STRIDE + PLG;
        float mx = lg[0];
        #pragma unroll
        for (int q = 1; q < 10; q++) mx = fmaxf(mx, lg[q]);
        float sum = 0.0f;
        #pragma unroll
        for (int q = 0; q < 10; q++) sum += expf(lg[q] - mx);
        s[SH_IMG0 + tid * IMG_STRIDE + PLG + 12] = mx + logf(sum);
    }
    __syncthreads();
    if (tid < 20) {
        const int img = tid / 10;
        const int o   = tid - img * 10;
        if (i0 + img < N) {
            const float* lg = s + SH_IMG0 + img * IMG_STRIDE + PLG;
            out[(i0 + img) * 10 + o] = lg[o] - lg[12];
        }
    }
}

extern "C" void kernel_launch(void* const* d_in, const int* in_sizes, int n_in,
                              void* d_out, int out_size) {
    const float* x        = (const float*)d_in[0];
    const float* kf_w1    = (const float*)d_in[1];
    const float* kf_b1    = (const float*)d_in[2];
    const float* kf_w2    = (const float*)d_in[3];
    const float* kf_b2    = (const float*)d_in[4];
    const float* kf_fc1_w = (const float*)d_in[5];
    const float* kf_fc1_b = (const float*)d_in[6];
    const float* kf_fc2_w = (const float*)d_in[7];
    const float* kf_fc2_b = (const float*)d_in[8];
    const float* conv2_w  = (const float*)d_in[9];
    const float* conv2_b  = (const float*)d_in[10];
    const float* fc1_w    = (const float*)d_in[11];
    const float* fc1_b    = (const float*)d_in[12];
    const float* fc2_w    = (const float*)d_in[13];
    const float* fc2_b    = (const float*)d_in[14];
    float* out = (float*)d_out;

    const int N = in_sizes[0] / 784;
    const int grid = (N + 1) / 2;
    cudaFuncSetAttribute(fused_net_kernel,
                         cudaFuncAttributeMaxDynamicSharedMemorySize, SMEM_BYTES);
    fused_net_kernel<<<grid, TPB, SMEM_BYTES>>>(x, kf_w1, kf_b1, kf_w2, kf_b2,
                                                kf_fc1_w, kf_fc1_b, kf_fc2_w, kf_fc2_b,
                                                conv2_w, conv2_b, fc1_w, fc1_b,
                                                fc2_w, fc2_b, out, N);
}

// round 13
// speedup vs baseline: 1.2741x; 1.0062x over previous
#include <cuda_runtime.h>
#include <math.h>

#define TPB 320
typedef unsigned long long u64;

// ---- packed fp32x2 helpers (sm_103a) ----
__device__ __forceinline__ u64 packdup(float a) {
    u64 r; asm("mov.b64 %0,{%1,%1};" : "=l"(r) : "f"(a)); return r;
}
__device__ __forceinline__ u64 fma2(u64 a, u64 b, u64 c) {
    u64 d; asm("fma.rn.f32x2 %0,%1,%2,%3;" : "=l"(d) : "l"(a), "l"(b), "l"(c)); return d;
}
__device__ __forceinline__ void unpk(u64 x, float& lo, float& hi) {
    asm("mov.b64 {%0,%1},%2;" : "=f"(lo), "=f"(hi) : "l"(x));
}

// ---- shared memory layout (floats) ----
#define OFF_W1Q 0        // ull2[2cpq][49 tap]                              (392)
#define OFF_W2P 392      // [5 pair][8ci][25] x2                            (2000)
#define OFF_CWQ 2392     // ull2[5cpq][10ci][25 tap]                        (5000)
#define OFF_B1P 7392     // (8)
#define OFF_B2P 7400     // (10)
#define OFF_CBP 7410     // (20) -> 7430 pad 7432
// per-image blocks (x2)
#define SH_IMG0 7432
#define IMG_STRIDE 2768
#define PX   0                // [28][28] (784); dead after S4 -> aliased below
#define PBUF 784              // pooled1 [8][11][12]=1056 / pooled3 [10][13][14]=1820
#define PF   2604             // (90)
#define PH   2694             // (32)
#define PK   2726             // (40) -> 2766 pad 2768
#define PP4  0                // [20][4][4] (320)  -- aliases PX (dead)
#define PY1  320              // (64)              -- aliases PX
#define PLG  384              // (16)              -- aliases PX
#define SMEM_FLOATS (SH_IMG0 + 2 * IMG_STRIDE)
#define SMEM_BYTES  (SMEM_FLOATS * 4)

__global__ __launch_bounds__(TPB, 3) void fused_net_kernel(
    const float* __restrict__ x,
    const float* __restrict__ kf_w1, const float* __restrict__ kf_b1,
    const float* __restrict__ kf_w2, const float* __restrict__ kf_b2,
    const float* __restrict__ kf_fc1_w, const float* __restrict__ kf_fc1_b,
    const float* __restrict__ kf_fc2_w, const float* __restrict__ kf_fc2_b,
    const float* __restrict__ conv2_w, const float* __restrict__ conv2_b,
    const float* __restrict__ fc1_w, const float* __restrict__ fc1_b,
    const float* __restrict__ fc2_w, const float* __restrict__ fc2_b,
    float* __restrict__ out, int N)
{
    extern __shared__ __align__(16) float s[];

    const int bn  = blockIdx.x;
    const int tid = threadIdx.x;
    const int i0  = 2 * bn;
    const int warp = tid >> 5;
    const int lane = tid & 31;

    // ================= Stage 0: stage inputs into smem =================
    {
        #pragma unroll
        for (int img = 0; img < 2; img++) {
            if (i0 + img < N) {
                const float4* x4 = (const float4*)(x + (i0 + img) * 784);
                float4* sx4 = (float4*)(s + SH_IMG0 + img * IMG_STRIDE + PX);
                for (int i = tid; i < 196; i += TPB) sx4[i] = x4[i];
            }
        }
        for (int i = tid; i < 392; i += TPB) {
            int c = i / 49, q = i - c * 49;
            int cpq = c >> 2, pr = (c >> 1) & 1, ch = c & 1;
            s[OFF_W1Q + ((cpq * 49 + q) * 2 + pr) * 2 + ch] = kf_w1[i];
        }
        for (int i = tid; i < 2000; i += TPB) {
            int c = i / 200, r = i - c * 200;
            s[OFF_W2P + (((c >> 1) * 200 + r) << 1) + (c & 1)] = kf_w2[i];
        }
        for (int i = tid; i < 5000; i += TPB) {
            int c = i / 250, r250 = i - c * 250;
            int ci = r250 / 25, q = r250 - ci * 25;
            int cpq = c >> 2, pr = (c >> 1) & 1, ch = c & 1;
            s[OFF_CWQ + (((cpq * 10 + ci) * 25 + q) * 2 + pr) * 2 + ch] = conv2_w[i];
        }
        if (tid < 8)  s[OFF_B1P + tid] = kf_b1[tid];
        if (tid < 10) s[OFF_B2P + tid] = kf_b2[tid];
        if (tid < 20) s[OFF_CBP + tid] = conv2_b[tid];
    }
    __syncthreads();

    // ===== Stage 1: conv7x7 (1->8) + pool + relu -> pooled1 [8][11][12pad] =====
    // unit = (cpq, img, pos). 484 units, 4 out channels per thread.
    // Weight-row-major loop with sliding 2-row activation window:
    // weights AND activations each loaded exactly once.
    for (int u = tid; u < 484; u += TPB) {
        const int cpq = u / 242;
        const int rem = u - cpq * 242;
        const int img = rem / 121;
        const int pos = rem - img * 121;
        const int pi  = pos / 11;
        const int pj  = pos - pi * 11;
        const float* sx = s + SH_IMG0 + img * IMG_STRIDE + PX;
        const ulonglong2* wq = (const ulonglong2*)(s + OFF_W1Q) + cpq * 49;
        const u64 b0 = ((const u64*)(s + OFF_B1P))[2 * cpq];
        const u64 b1 = ((const u64*)(s + OFF_B1P))[2 * cpq + 1];
        u64 A0[4] = {b0, b0, b0, b0};
        u64 A1[4] = {b1, b1, b1, b1};
        u64 pdbuf[2][8];
        // preload activation row 0 into pdbuf[0]
        {
            const float2* row = (const float2*)(sx + (2 * pi) * 28 + 2 * pj);
            #pragma unroll
            for (int j = 0; j < 4; j++) {
                float2 f = row[j];
                pdbuf[0][2 * j]     = packdup(f.x);
                pdbuf[0][2 * j + 1] = packdup(f.y);
            }
        }
        #pragma unroll
        for (int wr = 0; wr < 7; wr++) {
            const int prv = wr & 1;
            const int cur = prv ^ 1;
            // load activation row wr+1 into pdbuf[cur]
            {
                const float2* row = (const float2*)(sx + (2 * pi + wr + 1) * 28 + 2 * pj);
                #pragma unroll
                for (int j = 0; j < 4; j++) {
                    float2 f = row[j];
                    pdbuf[cur][2 * j]     = packdup(f.x);
                    pdbuf[cur][2 * j + 1] = packdup(f.y);
                }
            }
            #pragma unroll
            for (int v = 0; v < 7; v++) {
                const ulonglong2 w = wq[wr * 7 + v];
                // window-row 0 uses act row wr (prv)
                A0[0] = fma2(pdbuf[prv][v],     w.x, A0[0]);
                A0[1] = fma2(pdbuf[prv][v + 1], w.x, A0[1]);
                A1[0] = fma2(pdbuf[prv][v],     w.y, A1[0]);
                A1[1] = fma2(pdbuf[prv][v + 1], w.y, A1[1]);
                // window-row 1 uses act row wr+1 (cur)
                A0[2] = fma2(pdbuf[cur][v],     w.x, A0[2]);
                A0[3] = fma2(pdbuf[cur][v + 1], w.x, A0[3]);
                A1[2] = fma2(pdbuf[cur][v],     w.y, A1[2]);
                A1[3] = fma2(pdbuf[cur][v + 1], w.y, A1[3]);
            }
        }
        float* buf = s + SH_IMG0 + img * IMG_STRIDE + PBUF;
        {
            float p0, p1, q0, q1, r0, r1, t0, t1;
            unpk(A0[0], p0, p1); unpk(A0[1], q0, q1); unpk(A0[2], r0, r1); unpk(A0[3], t0, t1);
            buf[(4 * cpq)     * 132 + pi * 12 + pj] =
                fmaxf(fmaxf(fmaxf(p0, q0), fmaxf(r0, t0)), 0.0f);
            buf[(4 * cpq + 1) * 132 + pi * 12 + pj] =
                fmaxf(fmaxf(fmaxf(p1, q1), fmaxf(r1, t1)), 0.0f);
            unpk(A1[0], p0, p1); unpk(A1[1], q0, q1); unpk(A1[2], r0, r1); unpk(A1[3], t0, t1);
            buf[(4 * cpq + 2) * 132 + pi * 12 + pj] =
                fmaxf(fmaxf(fmaxf(p0, q0), fmaxf(r0, t0)), 0.0f);
            buf[(4 * cpq + 3) * 132 + pi * 12 + pj] =
                fmaxf(fmaxf(fmaxf(p1, q1), fmaxf(r1, t1)), 0.0f);
        }
    }
    __syncthreads();

    // ===== Stage 2: conv5x5 (8->10) + pool + relu -> f [10][3][3] =====
    if (tid < 192) {
        const int uu   = tid >> 1;
        const int half = tid & 1;
        const bool valid = uu < 90;
        const int u   = valid ? uu : 0;
        const int img = u / 45;
        const int t   = u - img * 45;
        const int cp  = t / 9;
        const int pos = t - cp * 9;
        const int pi  = pos / 3;
        const int pj  = pos - pi * 3;
        const float* buf = s + SH_IMG0 + img * IMG_STRIDE + PBUF;
        const u64 bias = ((const u64*)(s + OFF_B2P))[cp];
        u64 A[4];
        #pragma unroll
        for (int k = 0; k < 4; k++) A[k] = half ? 0ull : bias;
        u64 w[5];
        #pragma unroll
        for (int cc = 0; cc < 4; cc++) {
            const int ci = 4 * half + cc;
            const u64* wp = (const u64*)(s + OFF_W2P) + (cp * 8 + ci) * 25;
            #pragma unroll
            for (int r = 0; r < 6; r++) {
                const float2* row = (const float2*)(buf + ci * 132 + (2 * pi + r) * 12 + 2 * pj);
                u64 pd[6];
                #pragma unroll
                for (int j = 0; j < 3; j++) {
                    float2 f = row[j];
                    pd[2 * j]     = packdup(f.x);
                    pd[2 * j + 1] = packdup(f.y);
                }
                if (r >= 1) {
                    #pragma unroll
                    for (int v = 0; v < 5; v++) {
                        A[2] = fma2(pd[v],     w[v], A[2]);
                        A[3] = fma2(pd[v + 1], w[v], A[3]);
                    }
                }
                if (r < 5) {
                    #pragma unroll
                    for (int v = 0; v < 5; v++) {
                        w[v] = wp[r * 5 + v];
                        A[0] = fma2(pd[v],     w[v], A[0]);
                        A[1] = fma2(pd[v + 1], w[v], A[1]);
                    }
                }
            }
        }
        float me = -INFINITY, mo = -INFINITY;
        #pragma unroll
        for (int k = 0; k < 4; k++) {
            float lo, hi;
            unpk(A[k], lo, hi);
            lo += __shfl_xor_sync(0xffffffffu, lo, 1);
            hi += __shfl_xor_sync(0xffffffffu, hi, 1);
            me = fmaxf(me, lo);
            mo = fmaxf(mo, hi);
        }
        if (valid) {
            float* f = s + SH_IMG0 + img * IMG_STRIDE + PF;
            if (half == 0) f[(2 * cp)     * 9 + pos] = fmaxf(me, 0.0f);
            else           f[(2 * cp + 1) * 9 + pos] = fmaxf(mo, 0.0f);
        }
    }
    __syncthreads();

    // ===== Stage 3a: hypernet fc1 90->32 relu =====
    for (int u = warp; u < 64; u += (TPB / 32)) {
        const int img = u >> 5;
        const int o   = u & 31;
        const float* f  = s + SH_IMG0 + img * IMG_STRIDE + PF;
        const float* wr = kf_fc1_w + o * 90;
        float acc = 0.0f;
        #pragma unroll
        for (int k = 0; k < 3; k++) {
            const int q = lane + 32 * k;
            if (q < 90) acc = fmaf(f[q], wr[q], acc);
        }
        #pragma unroll
        for (int off = 16; off > 0; off >>= 1)
            acc += __shfl_xor_sync(0xffffffffu, acc, off);
        if (lane == 0)
            s[SH_IMG0 + img * IMG_STRIDE + PH + o] = fmaxf(acc + kf_fc1_b[o], 0.0f);
    }
    __syncthreads();

    // ===== Stage 3b: hypernet fc2 32->40 =====
    for (int u = warp; u < 80; u += (TPB / 32)) {
        const int img = u / 40;
        const int o   = u - img * 40;
        const float* h = s + SH_IMG0 + img * IMG_STRIDE + PH;
        float acc = h[lane] * kf_fc2_w[o * 32 + lane];
        #pragma unroll
        for (int off = 16; off > 0; off >>= 1)
            acc += __shfl_xor_sync(0xffffffffu, acc, off);
        if (lane == 0)
            s[SH_IMG0 + img * IMG_STRIDE + PK + o] = acc + kf_fc2_b[o];
    }
    __syncthreads();

    // ===== Stage 4: dynamic 2x2 conv + pool + relu -> pooled3 [10][13][14pad] =====
    for (int it = tid; it < 3380; it += TPB) {
        const int img = it / 1690;
        const int t   = it - img * 1690;
        const int c   = t / 169;
        const int rem = t - c * 169;
        const int pi  = rem / 13;
        const int pj  = rem - pi * 13;
        const float* base = s + SH_IMG0 + img * IMG_STRIDE;
        const float k00 = base[PK + c * 4 + 0];
        const float k01 = base[PK + c * 4 + 1];
        const float k10 = base[PK + c * 4 + 2];
        const float k11 = base[PK + c * 4 + 3];
        float a[3][3];
        #pragma unroll
        for (int u2 = 0; u2 < 3; u2++) {
            const float2 f01 = *(const float2*)(base + PX + (2 * pi + u2) * 28 + 2 * pj);
            a[u2][0] = f01.x; a[u2][1] = f01.y;
            a[u2][2] = base[PX + (2 * pi + u2) * 28 + 2 * pj + 2];
        }
        float m = -INFINITY;
        #pragma unroll
        for (int di = 0; di < 2; di++)
            #pragma unroll
            for (int dj = 0; dj < 2; dj++) {
                float cv = a[di][dj] * k00;
                cv = fmaf(a[di][dj + 1],     k01, cv);
                cv = fmaf(a[di + 1][dj],     k10, cv);
                cv = fmaf(a[di + 1][dj + 1], k11, cv);
                m = fmaxf(m, cv);
            }
        s[SH_IMG0 + img * IMG_STRIDE + PBUF + c * 182 + pi * 14 + pj] = fmaxf(m, 0.0f);
    }
    __syncthreads();

    // ===== Stage 5: conv5x5 (10->20) + pool + relu -> pooled4 [20][4][4] =====
    // 320 threads: warp = (cpq, img); lane bit4 = ci-half; shfl_xor(16) combine.
    {
        const int cpq = warp >> 1;
        const int img = warp & 1;
        const int cih = lane >> 4;
        const int pos = lane & 15;
        const int pi  = pos >> 2;
        const int pj  = pos & 3;
        const float* buf = s + SH_IMG0 + img * IMG_STRIDE + PBUF;
        const u64 b0 = ((const u64*)(s + OFF_CBP))[2 * cpq];
        const u64 b1 = ((const u64*)(s + OFF_CBP))[2 * cpq + 1];
        u64 A0[4], A1[4];
        #pragma unroll
        for (int k = 0; k < 4; k++) {
            A0[k] = cih ? 0ull : b0;
            A1[k] = cih ? 0ull : b1;
        }
        ulonglong2 w[5];
        #pragma unroll
        for (int cc = 0; cc < 5; cc++) {
            const int ci = 5 * cih + cc;
            const ulonglong2* wq = (const ulonglong2*)(s + OFF_CWQ) + (cpq * 10 + ci) * 25;
            #pragma unroll
            for (int r = 0; r < 6; r++) {
                const float2* row = (const float2*)(buf + ci * 182 + (2 * pi + r) * 14 + 2 * pj);
                u64 pd[6];
                #pragma unroll
                for (int j = 0; j < 3; j++) {
                    float2 f = row[j];
                    pd[2 * j]     = packdup(f.x);
                    pd[2 * j + 1] = packdup(f.y);
                }
                if (r >= 1) {
                    #pragma unroll
                    for (int v = 0; v < 5; v++) {
                        A0[2] = fma2(pd[v],     w[v].x, A0[2]);
                        A0[3] = fma2(pd[v + 1], w[v].x, A0[3]);
                        A1[2] = fma2(pd[v],     w[v].y, A1[2]);
                        A1[3] = fma2(pd[v + 1], w[v].y, A1[3]);
                    }
                }
                if (r < 5) {
                    #pragma unroll
                    for (int v = 0; v < 5; v++) {
                        w[v] = wq[r * 5 + v];
                        A0[0] = fma2(pd[v],     w[v].x, A0[0]);
                        A0[1] = fma2(pd[v + 1], w[v].x, A0[1]);
                        A1[0] = fma2(pd[v],     w[v].y, A1[0]);
                        A1[1] = fma2(pd[v + 1], w[v].y, A1[1]);
                    }
                }
            }
        }
        float* p4 = s + SH_IMG0 + img * IMG_STRIDE + PP4;
        {
            float m0 = -INFINITY, m1 = -INFINITY;
            #pragma unroll
            for (int k = 0; k < 4; k++) {
                float lo, hi;
                unpk(A0[k], lo, hi);
                lo += __shfl_xor_sync(0xffffffffu, lo, 16);
                hi += __shfl_xor_sync(0xffffffffu, hi, 16);
                m0 = fmaxf(m0, lo);
                m1 = fmaxf(m1, hi);
            }
            if (cih == 0) {
                p4[(4 * cpq)     * 16 + pos] = fmaxf(m0, 0.0f);
                p4[(4 * cpq + 1) * 16 + pos] = fmaxf(m1, 0.0f);
            }
        }
        {
            float m0 = -INFINITY, m1 = -INFINITY;
            #pragma unroll
            for (int k = 0; k < 4; k++) {
                float lo, hi;
                unpk(A1[k], lo, hi);
                lo += __shfl_xor_sync(0xffffffffu, lo, 16);
                hi += __shfl_xor_sync(0xffffffffu, hi, 16);
                m0 = fmaxf(m0, lo);
                m1 = fmaxf(m1, hi);
            }
            if (cih == 0) {
                p4[(4 * cpq + 2) * 16 + pos] = fmaxf(m0, 0.0f);
                p4[(4 * cpq + 3) * 16 + pos] = fmaxf(m1, 0.0f);
            }
        }
    }
    __syncthreads();

    // ===== Stage 6: fc1 320->50 relu — warp per o, weights loaded once for BOTH imgs =====
    for (int o = warp; o < 50; o += (TPB / 32)) {
        const float4* wr = (const float4*)(fc1_w + o * 320);
        float4 w4[3];
        #pragma unroll
        for (int k = 0; k < 3; k++) {
            const int i = lane + 32 * k;
            w4[k] = (i < 80) ? wr[i] : make_float4(0.f, 0.f, 0.f, 0.f);
        }
        #pragma unroll
        for (int img = 0; img < 2; img++) {
            const float4* pr = (const float4*)(s + SH_IMG0 + img * IMG_STRIDE + PP4);
            float acc = 0.0f;
            #pragma unroll
            for (int k = 0; k < 3; k++) {
                const int i = lane + 32 * k;
                if (i < 80) {
                    float4 p4 = pr[i];
                    acc = fmaf(w4[k].x, p4.x, fmaf(w4[k].y, p4.y,
                          fmaf(w4[k].z, p4.z, fmaf(w4[k].w, p4.w, acc))));
                }
            }
            #pragma unroll
            for (int off = 16; off > 0; off >>= 1)
                acc += __shfl_xor_sync(0xffffffffu, acc, off);
            if (lane == 0)
                s[SH_IMG0 + img * IMG_STRIDE + PY1 + o] = fmaxf(acc + fc1_b[o], 0.0f);
        }
    }
    __syncthreads();

    // ===== Stage 7: fc2 50->10 — warp per (img,o) =====
    for (int u = warp; u < 20; u += (TPB / 32)) {
        const int img = u / 10;
        const int o   = u - img * 10;
        const float* y1 = s + SH_IMG0 + img * IMG_STRIDE + PY1;
        const float* wr = fc2_w + o * 50;
        float acc = y1[lane] * wr[lane];
        const int q = lane + 32;
        if (q < 50) acc = fmaf(y1[q], wr[q], acc);
        #pragma unroll
        for (int off = 16; off > 0; off >>= 1)
            acc += __shfl_xor_sync(0xffffffffu, acc, off);
        if (lane == 0)
            s[SH_IMG0 + img * IMG_STRIDE + PLG + o] = acc + fc2_b[o];
    }
    __syncthreads();
    if (tid < 2) {
        const float* lg = s + SH_IMG0 + tid * IMG_STRIDE + PLG;
        float mx = lg[0];
        #pragma unroll
        for (int q = 1; q < 10; q++) mx = fmaxf(mx, lg[q]);
        float sum = 0.0f;
        #pragma unroll
        for (int q = 0; q < 10; q++) sum += expf(lg[q] - mx);
        s[SH_IMG0 + tid * IMG_STRIDE + PLG + 12] = mx + logf(sum);
    }
    __syncthreads();
    if (tid < 20) {
        const int img = tid / 10;
        const int o   = tid - img * 10;
        if (i0 + img < N) {
            const float* lg = s + SH_IMG0 + img * IMG_STRIDE + PLG;
            out[(i0 + img) * 10 + o] = lg[o] - lg[12];
        }
    }
}

extern "C" void kernel_launch(void* const* d_in, const int* in_sizes, int n_in,
                              void* d_out, int out_size) {
    const float* x        = (const float*)d_in[0];
    const float* kf_w1    = (const float*)d_in[1];
    const float* kf_b1    = (const float*)d_in[2];
    const float* kf_w2    = (const float*)d_in[3];
    const float* kf_b2    = (const float*)d_in[4];
    const float* kf_fc1_w = (const float*)d_in[5];
    const float* kf_fc1_b = (const float*)d_in[6];
    const float* kf_fc2_w = (const float*)d_in[7];
    const float* kf_fc2_b = (const float*)d_in[8];
    const float* conv2_w  = (const float*)d_in[9];
    const float* conv2_b  = (const float*)d_in[10];
    const float* fc1_w    = (const float*)d_in[11];
    const float* fc1_b    = (const float*)d_in[12];
    const float* fc2_w    = (const float*)d_in[13];
    const float* fc2_b    = (const float*)d_in[14];
    float* out = (float*)d_out;

    const int N = in_sizes[0] / 784;
    const int grid = (N + 1) / 2;
    cudaFuncSetAttribute(fused_net_kernel,
                         cudaFuncAttributeMaxDynamicSharedMemorySize, SMEM_BYTES);
    fused_net_kernel<<<grid, TPB, SMEM_BYTES>>>(x, kf_w1, kf_b1, kf_w2, kf_b2,
                                                kf_fc1_w, kf_fc1_b, kf_fc2_w, kf_fc2_b,
                                                conv2_w, conv2_b, fc1_w, fc1_b,
                                                fc2_w, fc2_b, out, N);
}

// round 14
// speedup vs baseline: 1.3725x; 1.0772x over previous
#include <cuda_runtime.h>
#include <math.h>

#define TPB 320
typedef unsigned long long u64;

// ---- packed fp32x2 helpers (sm_103a) ----
__device__ __forceinline__ u64 packdup(float a) {
    u64 r; asm("mov.b64 %0,{%1,%1};" : "=l"(r) : "f"(a)); return r;
}
__device__ __forceinline__ u64 fma2(u64 a, u64 b, u64 c) {
    u64 d; asm("fma.rn.f32x2 %0,%1,%2,%3;" : "=l"(d) : "l"(a), "l"(b), "l"(c)); return d;
}
__device__ __forceinline__ void unpk(u64 x, float& lo, float& hi) {
    asm("mov.b64 {%0,%1},%2;" : "=f"(lo), "=f"(hi) : "l"(x));
}

// ---- shared memory layout (floats) ----
#define OFF_W1Q 0        // ull2[2cpq][49 tap]                              (392)
#define OFF_W2P 392      // [5 pair][8ci][25] x2                            (2000)
#define OFF_CWQ 2392     // ull2[5cpq][10ci][25 tap]                        (5000)
#define OFF_B1P 7392     // (8)
#define OFF_B2P 7400     // (10)
#define OFF_CBP 7410     // (20) -> 7430 pad 7432
// per-image blocks (x2)
#define SH_IMG0 7432
#define IMG_STRIDE 2768
#define PX   0                // [28][28] (784); dead after S4 -> aliased below
#define PBUF 784              // pooled1 [8][11][12]=1056 / pooled3 [10][13][14]=1820
#define PF   2604             // (90)
#define PH   2694             // (32) -> 2726 pad to 2728 (16B align for PK float4)
#define PK   2728             // (40) -> 2768
#define PP4  0                // [20][4][4] (320)  -- aliases PX (dead)
#define PY1  320              // (64)              -- aliases PX
#define PLG  384              // (16)              -- aliases PX
#define SMEM_FLOATS (SH_IMG0 + 2 * IMG_STRIDE)
#define SMEM_BYTES  (SMEM_FLOATS * 4)

__global__ __launch_bounds__(TPB, 3) void fused_net_kernel(
    const float* __restrict__ x,
    const float* __restrict__ kf_w1, const float* __restrict__ kf_b1,
    const float* __restrict__ kf_w2, const float* __restrict__ kf_b2,
    const float* __restrict__ kf_fc1_w, const float* __restrict__ kf_fc1_b,
    const float* __restrict__ kf_fc2_w, const float* __restrict__ kf_fc2_b,
    const float* __restrict__ conv2_w, const float* __restrict__ conv2_b,
    const float* __restrict__ fc1_w, const float* __restrict__ fc1_b,
    const float* __restrict__ fc2_w, const float* __restrict__ fc2_b,
    float* __restrict__ out, int N)
{
    extern __shared__ __align__(16) float s[];

    const int bn  = blockIdx.x;
    const int tid = threadIdx.x;
    const int i0  = 2 * bn;
    const int warp = tid >> 5;
    const int lane = tid & 31;

    // ================= Stage 0: stage inputs into smem =================
    {
        #pragma unroll
        for (int img = 0; img < 2; img++) {
            if (i0 + img < N) {
                const float4* x4 = (const float4*)(x + (i0 + img) * 784);
                float4* sx4 = (float4*)(s + SH_IMG0 + img * IMG_STRIDE + PX);
                for (int i = tid; i < 196; i += TPB) sx4[i] = x4[i];
            }
        }
        for (int i = tid; i < 392; i += TPB) {
            int c = i / 49, q = i - c * 49;
            int cpq = c >> 2, pr = (c >> 1) & 1, ch = c & 1;
            s[OFF_W1Q + ((cpq * 49 + q) * 2 + pr) * 2 + ch] = kf_w1[i];
        }
        for (int i = tid; i < 2000; i += TPB) {
            int c = i / 200, r = i - c * 200;
            s[OFF_W2P + (((c >> 1) * 200 + r) << 1) + (c & 1)] = kf_w2[i];
        }
        for (int i = tid; i < 5000; i += TPB) {
            int c = i / 250, r250 = i - c * 250;
            int ci = r250 / 25, q = r250 - ci * 25;
            int cpq = c >> 2, pr = (c >> 1) & 1, ch = c & 1;
            s[OFF_CWQ + (((cpq * 10 + ci) * 25 + q) * 2 + pr) * 2 + ch] = conv2_w[i];
        }
        if (tid < 8)  s[OFF_B1P + tid] = kf_b1[tid];
        if (tid < 10) s[OFF_B2P + tid] = kf_b2[tid];
        if (tid < 20) s[OFF_CBP + tid] = conv2_b[tid];
    }
    __syncthreads();

    // ===== Stage 1: conv7x7 (1->8) + pool + relu -> pooled1 [8][11][12pad] =====
    // Weight-row-major loop, sliding 2-row activation window: each loaded once.
    for (int u = tid; u < 484; u += TPB) {
        const int cpq = u / 242;
        const int rem = u - cpq * 242;
        const int img = rem / 121;
        const int pos = rem - img * 121;
        const int pi  = pos / 11;
        const int pj  = pos - pi * 11;
        const float* sx = s + SH_IMG0 + img * IMG_STRIDE + PX;
        const ulonglong2* wq = (const ulonglong2*)(s + OFF_W1Q) + cpq * 49;
        const u64 b0 = ((const u64*)(s + OFF_B1P))[2 * cpq];
        const u64 b1 = ((const u64*)(s + OFF_B1P))[2 * cpq + 1];
        u64 A0[4] = {b0, b0, b0, b0};
        u64 A1[4] = {b1, b1, b1, b1};
        u64 pdbuf[2][8];
        {
            const float2* row = (const float2*)(sx + (2 * pi) * 28 + 2 * pj);
            #pragma unroll
            for (int j = 0; j < 4; j++) {
                float2 f = row[j];
                pdbuf[0][2 * j]     = packdup(f.x);
                pdbuf[0][2 * j + 1] = packdup(f.y);
            }
        }
        #pragma unroll
        for (int wr = 0; wr < 7; wr++) {
            const int prv = wr & 1;
            const int cur = prv ^ 1;
            {
                const float2* row = (const float2*)(sx + (2 * pi + wr + 1) * 28 + 2 * pj);
                #pragma unroll
                for (int j = 0; j < 4; j++) {
                    float2 f = row[j];
                    pdbuf[cur][2 * j]     = packdup(f.x);
                    pdbuf[cur][2 * j + 1] = packdup(f.y);
                }
            }
            #pragma unroll
            for (int v = 0; v < 7; v++) {
                const ulonglong2 w = wq[wr * 7 + v];
                A0[0] = fma2(pdbuf[prv][v],     w.x, A0[0]);
                A0[1] = fma2(pdbuf[prv][v + 1], w.x, A0[1]);
                A1[0] = fma2(pdbuf[prv][v],     w.y, A1[0]);
                A1[1] = fma2(pdbuf[prv][v + 1], w.y, A1[1]);
                A0[2] = fma2(pdbuf[cur][v],     w.x, A0[2]);
                A0[3] = fma2(pdbuf[cur][v + 1], w.x, A0[3]);
                A1[2] = fma2(pdbuf[cur][v],     w.y, A1[2]);
                A1[3] = fma2(pdbuf[cur][v + 1], w.y, A1[3]);
            }
        }
        float* buf = s + SH_IMG0 + img * IMG_STRIDE + PBUF;
        {
            float p0, p1, q0, q1, r0, r1, t0, t1;
            unpk(A0[0], p0, p1); unpk(A0[1], q0, q1); unpk(A0[2], r0, r1); unpk(A0[3], t0, t1);
            buf[(4 * cpq)     * 132 + pi * 12 + pj] =
                fmaxf(fmaxf(fmaxf(p0, q0), fmaxf(r0, t0)), 0.0f);
            buf[(4 * cpq + 1) * 132 + pi * 12 + pj] =
                fmaxf(fmaxf(fmaxf(p1, q1), fmaxf(r1, t1)), 0.0f);
            unpk(A1[0], p0, p1); unpk(A1[1], q0, q1); unpk(A1[2], r0, r1); unpk(A1[3], t0, t1);
            buf[(4 * cpq + 2) * 132 + pi * 12 + pj] =
                fmaxf(fmaxf(fmaxf(p0, q0), fmaxf(r0, t0)), 0.0f);
            buf[(4 * cpq + 3) * 132 + pi * 12 + pj] =
                fmaxf(fmaxf(fmaxf(p1, q1), fmaxf(r1, t1)), 0.0f);
        }
    }
    __syncthreads();

    // ===== Stage 2: conv5x5 (8->10) + pool + relu -> f [10][3][3] =====
    if (tid < 192) {
        const int uu   = tid >> 1;
        const int half = tid & 1;
        const bool valid = uu < 90;
        const int u   = valid ? uu : 0;
        const int img = u / 45;
        const int t   = u - img * 45;
        const int cp  = t / 9;
        const int pos = t - cp * 9;
        const int pi  = pos / 3;
        const int pj  = pos - pi * 3;
        const float* buf = s + SH_IMG0 + img * IMG_STRIDE + PBUF;
        const u64 bias = ((const u64*)(s + OFF_B2P))[cp];
        u64 A[4];
        #pragma unroll
        for (int k = 0; k < 4; k++) A[k] = half ? 0ull : bias;
        u64 w[5];
        #pragma unroll
        for (int cc = 0; cc < 4; cc++) {
            const int ci = 4 * half + cc;
            const u64* wp = (const u64*)(s + OFF_W2P) + (cp * 8 + ci) * 25;
            #pragma unroll
            for (int r = 0; r < 6; r++) {
                const float2* row = (const float2*)(buf + ci * 132 + (2 * pi + r) * 12 + 2 * pj);
                u64 pd[6];
                #pragma unroll
                for (int j = 0; j < 3; j++) {
                    float2 f = row[j];
                    pd[2 * j]     = packdup(f.x);
                    pd[2 * j + 1] = packdup(f.y);
                }
                if (r >= 1) {
                    #pragma unroll
                    for (int v = 0; v < 5; v++) {
                        A[2] = fma2(pd[v],     w[v], A[2]);
                        A[3] = fma2(pd[v + 1], w[v], A[3]);
                    }
                }
                if (r < 5) {
                    #pragma unroll
                    for (int v = 0; v < 5; v++) {
                        w[v] = wp[r * 5 + v];
                        A[0] = fma2(pd[v],     w[v], A[0]);
                        A[1] = fma2(pd[v + 1], w[v], A[1]);
                    }
                }
            }
        }
        float me = -INFINITY, mo = -INFINITY;
        #pragma unroll
        for (int k = 0; k < 4; k++) {
            float lo, hi;
            unpk(A[k], lo, hi);
            lo += __shfl_xor_sync(0xffffffffu, lo, 1);
            hi += __shfl_xor_sync(0xffffffffu, hi, 1);
            me = fmaxf(me, lo);
            mo = fmaxf(mo, hi);
        }
        if (valid) {
            float* f = s + SH_IMG0 + img * IMG_STRIDE + PF;
            if (half == 0) f[(2 * cp)     * 9 + pos] = fmaxf(me, 0.0f);
            else           f[(2 * cp + 1) * 9 + pos] = fmaxf(mo, 0.0f);
        }
    }
    __syncthreads();

    // ===== Stage 3a: hypernet fc1 90->32 relu =====
    for (int u = warp; u < 64; u += (TPB / 32)) {
        const int img = u >> 5;
        const int o   = u & 31;
        const float* f  = s + SH_IMG0 + img * IMG_STRIDE + PF;
        const float* wr = kf_fc1_w + o * 90;
        float acc = 0.0f;
        #pragma unroll
        for (int k = 0; k < 3; k++) {
            const int q = lane + 32 * k;
            if (q < 90) acc = fmaf(f[q], wr[q], acc);
        }
        #pragma unroll
        for (int off = 16; off > 0; off >>= 1)
            acc += __shfl_xor_sync(0xffffffffu, acc, off);
        if (lane == 0)
            s[SH_IMG0 + img * IMG_STRIDE + PH + o] = fmaxf(acc + kf_fc1_b[o], 0.0f);
    }
    __syncthreads();

    // ===== Stage 3b: hypernet fc2 32->40 =====
    for (int u = warp; u < 80; u += (TPB / 32)) {
        const int img = u / 40;
        const int o   = u - img * 40;
        const float* h = s + SH_IMG0 + img * IMG_STRIDE + PH;
        float acc = h[lane] * kf_fc2_w[o * 32 + lane];
        #pragma unroll
        for (int off = 16; off > 0; off >>= 1)
            acc += __shfl_xor_sync(0xffffffffu, acc, off);
        if (lane == 0)
            s[SH_IMG0 + img * IMG_STRIDE + PK + o] = acc + kf_fc2_b[o];
    }
    __syncthreads();

    // ===== Stage 4: dynamic 2x2 conv + pool + relu -> pooled3 [10][13][14pad] =====
    // thread = (img, pos); ALL 10 channels per thread: window read ONCE,
    // per-channel kernel = one broadcast LDS.128.
    for (int it = tid; it < 338; it += TPB) {
        const int img = it / 169;
        const int pos = it - img * 169;
        const int pi  = pos / 13;
        const int pj  = pos - pi * 13;
        float* base = s + SH_IMG0 + img * IMG_STRIDE;
        float a[3][3];
        #pragma unroll
        for (int u2 = 0; u2 < 3; u2++) {
            const float2 f01 = *(const float2*)(base + PX + (2 * pi + u2) * 28 + 2 * pj);
            a[u2][0] = f01.x; a[u2][1] = f01.y;
            a[u2][2] = base[PX + (2 * pi + u2) * 28 + 2 * pj + 2];
        }
        #pragma unroll
        for (int c = 0; c < 10; c++) {
            const float4 kv = *(const float4*)(base + PK + c * 4);
            float m = -INFINITY;
            #pragma unroll
            for (int di = 0; di < 2; di++)
                #pragma unroll
                for (int dj = 0; dj < 2; dj++) {
                    float cv = a[di][dj] * kv.x;
                    cv = fmaf(a[di][dj + 1],     kv.y, cv);
                    cv = fmaf(a[di + 1][dj],     kv.z, cv);
                    cv = fmaf(a[di + 1][dj + 1], kv.w, cv);
                    m = fmaxf(m, cv);
                }
            base[PBUF + c * 182 + pi * 14 + pj] = fmaxf(m, 0.0f);
        }
    }
    __syncthreads();

    // ===== Stage 5: conv5x5 (10->20) + pool + relu -> pooled4 [20][4][4] =====
    // 320 threads: warp = (cpq, img); lane bit4 = ci-half; shfl_xor(16) combine.
    {
        const int cpq = warp >> 1;
        const int img = warp & 1;
        const int cih = lane >> 4;
        const int pos = lane & 15;
        const int pi  = pos >> 2;
        const int pj  = pos & 3;
        const float* buf = s + SH_IMG0 + img * IMG_STRIDE + PBUF;
        const u64 b0 = ((const u64*)(s + OFF_CBP))[2 * cpq];
        const u64 b1 = ((const u64*)(s + OFF_CBP))[2 * cpq + 1];
        u64 A0[4], A1[4];
        #pragma unroll
        for (int k = 0; k < 4; k++) {
            A0[k] = cih ? 0ull : b0;
            A1[k] = cih ? 0ull : b1;
        }
        ulonglong2 w[5];
        #pragma unroll
        for (int cc = 0; cc < 5; cc++) {
            const int ci = 5 * cih + cc;
            const ulonglong2* wq = (const ulonglong2*)(s + OFF_CWQ) + (cpq * 10 + ci) * 25;
            #pragma unroll
            for (int r = 0; r < 6; r++) {
                const float2* row = (const float2*)(buf + ci * 182 + (2 * pi + r) * 14 + 2 * pj);
                u64 pd[6];
                #pragma unroll
                for (int j = 0; j < 3; j++) {
                    float2 f = row[j];
                    pd[2 * j]     = packdup(f.x);
                    pd[2 * j + 1] = packdup(f.y);
                }
                if (r >= 1) {
                    #pragma unroll
                    for (int v = 0; v < 5; v++) {
                        A0[2] = fma2(pd[v],     w[v].x, A0[2]);
                        A0[3] = fma2(pd[v + 1], w[v].x, A0[3]);
                        A1[2] = fma2(pd[v],     w[v].y, A1[2]);
                        A1[3] = fma2(pd[v + 1], w[v].y, A1[3]);
                    }
                }
                if (r < 5) {
                    #pragma unroll
                    for (int v = 0; v < 5; v++) {
                        w[v] = wq[r * 5 + v];
                        A0[0] = fma2(pd[v],     w[v].x, A0[0]);
                        A0[1] = fma2(pd[v + 1], w[v].x, A0[1]);
                        A1[0] = fma2(pd[v],     w[v].y, A1[0]);
                        A1[1] = fma2(pd[v + 1], w[v].y, A1[1]);
                    }
                }
            }
        }
        float* p4 = s + SH_IMG0 + img * IMG_STRIDE + PP4;
        {
            float m0 = -INFINITY, m1 = -INFINITY;
            #pragma unroll
            for (int k = 0; k < 4; k++) {
                float lo, hi;
                unpk(A0[k], lo, hi);
                lo += __shfl_xor_sync(0xffffffffu, lo, 16);
                hi += __shfl_xor_sync(0xffffffffu, hi, 16);
                m0 = fmaxf(m0, lo);
                m1 = fmaxf(m1, hi);
            }
            if (cih == 0) {
                p4[(4 * cpq)     * 16 + pos] = fmaxf(m0, 0.0f);
                p4[(4 * cpq + 1) * 16 + pos] = fmaxf(m1, 0.0f);
            }
        }
        {
            float m0 = -INFINITY, m1 = -INFINITY;
            #pragma unroll
            for (int k = 0; k < 4; k++) {
                float lo, hi;
                unpk(A1[k], lo, hi);
                lo += __shfl_xor_sync(0xffffffffu, lo, 16);
                hi += __shfl_xor_sync(0xffffffffu, hi, 16);
                m0 = fmaxf(m0, lo);
                m1 = fmaxf(m1, hi);
            }
            if (cih == 0) {
                p4[(4 * cpq + 2) * 16 + pos] = fmaxf(m0, 0.0f);
                p4[(4 * cpq + 3) * 16 + pos] = fmaxf(m1, 0.0f);
            }
        }
    }
    __syncthreads();

    // ===== Stage 6: fc1 320->50 relu — warp per o, weights loaded once for BOTH imgs =====
    for (int o = warp; o < 50; o += (TPB / 32)) {
        const float4* wr = (const float4*)(fc1_w + o * 320);
        float4 w4[3];
        #pragma unroll
        for (int k = 0; k < 3; k++) {
            const int i = lane + 32 * k;
            w4[k] = (i < 80) ? wr[i] : make_float4(0.f, 0.f, 0.f, 0.f);
        }
        #pragma unroll
        for (int img = 0; img < 2; img++) {
            const float4* pr = (const float4*)(s + SH_IMG0 + img * IMG_STRIDE + PP4);
            float acc = 0.0f;
            #pragma unroll
            for (int k = 0; k < 3; k++) {
                const int i = lane + 32 * k;
                if (i < 80) {
                    float4 p4 = pr[i];
                    acc = fmaf(w4[k].x, p4.x, fmaf(w4[k].y, p4.y,
                          fmaf(w4[k].z, p4.z, fmaf(w4[k].w, p4.w, acc))));
                }
            }
            #pragma unroll
            for (int off = 16; off > 0; off >>= 1)
                acc += __shfl_xor_sync(0xffffffffu, acc, off);
            if (lane == 0)
                s[SH_IMG0 + img * IMG_STRIDE + PY1 + o] = fmaxf(acc + fc1_b[o], 0.0f);
        }
    }
    __syncthreads();

    // ===== Stage 7: fc2 50->10 — warp per (img,o) =====
    for (int u = warp; u < 20; u += (TPB / 32)) {
        const int img = u / 10;
        const int o   = u - img * 10;
        const float* y1 = s + SH_IMG0 + img * IMG_STRIDE + PY1;
        const float* wr = fc2_w + o * 50;
        float acc = y1[lane] * wr[lane];
        const int q = lane + 32;
        if (q < 50) acc = fmaf(y1[q], wr[q], acc);
        #pragma unroll
        for (int off = 16; off > 0; off >>= 1)
            acc += __shfl_xor_sync(0xffffffffu, acc, off);
        if (lane == 0)
            s[SH_IMG0 + img * IMG_STRIDE + PLG + o] = acc + fc2_b[o];
    }
    __syncthreads();
    if (tid < 2) {
        const float* lg = s + SH_IMG0 + tid * IMG_STRIDE + PLG;
        float mx = lg[0];
        #pragma unroll
        for (int q = 1; q < 10; q++) mx = fmaxf(mx, lg[q]);
        float sum = 0.0f;
        #pragma unroll
        for (int q = 0; q < 10; q++) sum += expf(lg[q] - mx);
        s[SH_IMG0 + tid * IMG_STRIDE + PLG + 12] = mx + logf(sum);
    }
    __syncthreads();
    if (tid < 20) {
        const int img = tid / 10;
        const int o   = tid - img * 10;
        if (i0 + img < N) {
            const float* lg = s + SH_IMG0 + img * IMG_STRIDE + PLG;
            out[(i0 + img) * 10 + o] = lg[o] - lg[12];
        }
    }
}

extern "C" void kernel_launch(void* const* d_in, const int* in_sizes, int n_in,
                              void* d_out, int out_size) {
    const float* x        = (const float*)d_in[0];
    const float* kf_w1    = (const float*)d_in[1];
    const float* kf_b1    = (const float*)d_in[2];
    const float* kf_w2    = (const float*)d_in[3];
    const float* kf_b2    = (const float*)d_in[4];
    const float* kf_fc1_w = (const float*)d_in[5];
    const float* kf_fc1_b = (const float*)d_in[6];
    const float* kf_fc2_w = (const float*)d_in[7];
    const float* kf_fc2_b = (const float*)d_in[8];
    const float* conv2_w  = (const float*)d_in[9];
    const float* conv2_b  = (const float*)d_in[10];
    const float* fc1_w    = (const float*)d_in[11];
    const float* fc1_b    = (const float*)d_in[12];
    const float* fc2_w    = (const float*)d_in[13];
    const float* fc2_b    = (const float*)d_in[14];
    float* out = (float*)d_out;

    const int N = in_sizes[0] / 784;
    const int grid = (N + 1) / 2;
    cudaFuncSetAttribute(fused_net_kernel,
                         cudaFuncAttributeMaxDynamicSharedMemorySize, SMEM_BYTES);
    fused_net_kernel<<<grid, TPB, SMEM_BYTES>>>(x, kf_w1, kf_b1, kf_w2, kf_b2,
                                                kf_fc1_w, kf_fc1_b, kf_fc2_w, kf_fc2_b,
                                                conv2_w, conv2_b, fc1_w, fc1_b,
                                                fc2_w, fc2_b, out, N);
}